// round 12
// baseline (speedup 1.0000x reference)
#include <cuda_runtime.h>
#include <math.h>

// Problem constants
#define Bq 16
#define Dq 64
#define Sq 256
#define Hq 128
#define H3 384
#define NROW (Bq*Dq*Sq)   // 262144
#define BDq (Bq*Dq)       // 1024
#define NLOOP 10

// Scratch (device globals: allocation-free rule)
__device__ float g_node[NROW*Hq];
__device__ float g_tmp [NROW*Hq];
__device__ float g_agg [NROW*Hq];
__device__ float g_gi  [NROW*H3];
__device__ float g_gh  [NROW*H3];
__device__ float g_wiht[Hq*H3];
__device__ float g_whht[Hq*H3];

// ---------------------------------------------------------------------------
// FROZEN NUMERICS (R10-verified): XLA EmitFastTanh, unfused mul/add.
// ---------------------------------------------------------------------------
__device__ __forceinline__ float tanh_xla(float x){
    float ax = fabsf(x);
    if (ax < 0.0004f) return x;
    float xc = fminf(fmaxf(x, -7.90531110763549805f), 7.90531110763549805f);
    float a  = __fmul_rn(xc, xc);
    float p = __fadd_rn(__fmul_rn(a, -2.76076847742355e-16f), 2.00018790482477e-13f);
    p = __fadd_rn(__fmul_rn(a, p), -8.60467152213735e-11f);
    p = __fadd_rn(__fmul_rn(a, p),  5.12229709037114e-08f);
    p = __fadd_rn(__fmul_rn(a, p),  1.48572235717979e-05f);
    p = __fadd_rn(__fmul_rn(a, p),  6.37261928875436e-04f);
    p = __fadd_rn(__fmul_rn(a, p),  4.89352455891786e-03f);
    float num = __fmul_rn(xc, p);
    float q = __fadd_rn(__fmul_rn(a, 1.19825839466702e-06f), 1.18534705686654e-04f);
    q = __fadd_rn(__fmul_rn(a, q), 2.26843463243900e-03f);
    q = __fadd_rn(__fmul_rn(a, q), 4.89352518554385e-03f);
    return __fdiv_rn(num, q);
}

// FROZEN: Cephes/Eigen f32 exp, unfused.
__device__ __forceinline__ float exp_cephes(float x){
    x = fminf(x,  88.3762626647950f);
    x = fmaxf(x, -88.3762626647949f);
    float m = floorf(__fadd_rn(__fmul_rn(x, 1.44269504088896341f), 0.5f));
    float r = __fsub_rn(x, __fmul_rn(m, 0.693359375f));
    r = __fsub_rn(r, __fmul_rn(m, -2.12194440e-4f));
    float z = __fmul_rn(r, r);
    float y = 1.9875691500e-4f;
    y = __fadd_rn(__fmul_rn(y, r), 1.3981999507e-3f);
    y = __fadd_rn(__fmul_rn(y, r), 8.3334519073e-3f);
    y = __fadd_rn(__fmul_rn(y, r), 4.1665795894e-2f);
    y = __fadd_rn(__fmul_rn(y, r), 1.6666665459e-1f);
    y = __fadd_rn(__fmul_rn(y, r), 5.0000001201e-1f);
    y = __fadd_rn(__fmul_rn(y, z), r);
    y = __fadd_rn(y, 1.0f);
    int mi = (int)m;
    float s = __int_as_float((mi + 127) << 23);
    return __fmul_rn(y, s);
}

__device__ __forceinline__ float sigmoid_xla(float x){
    float e = exp_cephes(-x);
    return __fdiv_rn(1.f, __fadd_rn(1.f, e));
}

// ---------------------------------------------------------------------------
// Embedding gather: node[n][:] = embed[idx[n]][:]
// ---------------------------------------------------------------------------
__global__ void k_gather(const int* __restrict__ idx,
                         const float* __restrict__ embed,
                         float* __restrict__ node)
{
    size_t t = (size_t)blockIdx.x*blockDim.x + threadIdx.x;   // NROW*32 threads
    size_t n = t >> 5; int c = (int)(t & 31) << 2;
    float4 v = *(const float4*)(embed + (size_t)idx[n]*Hq + c);
    *(float4*)(node + n*Hq + c) = v;
}

// ---------------------------------------------------------------------------
// Weight transpose: wt[k][j] = w[j][k], w is [H3][Hq]
// ---------------------------------------------------------------------------
__global__ void k_transpose(const float* __restrict__ w, float* __restrict__ wt)
{
    int t = blockIdx.x*blockDim.x + threadIdx.x;
    if (t < H3*Hq){ int j = t / Hq, k = t % Hq; wt[k*H3 + j] = w[t]; }
}

// ---------------------------------------------------------------------------
// GEMM: C[row][c] = sum_k A[row][k]*W[k*ldw+c] (+bias, opt tanh)
// Sequential-k FMA chain per output — bit-identical to R10.
// Block: 256 threads, 256 rows x 128 cols, thread tile 8x16.
// smem: As[128][256] (128KB) + Ws[128][128] (64KB) = 192KB, 1 CTA/SM.
// Intensity: 24 smem floats per 128 FMAs = 0.75 B/FMA (under crossbar knee).
// blockIdx.y = 128-column chunk (W/bias/C offset by y*128).
// ---------------------------------------------------------------------------
__global__ __launch_bounds__(256, 1)
void k_gemm(const float* __restrict__ A,
            const float* __restrict__ W, int ldw,
            const float* __restrict__ bias,
            float* __restrict__ C, int ldc, int act)
{
    extern __shared__ float smem[];
    float* As = smem;              // 128 k x 256 r   [k][r]
    float* Ws = smem + 128*256;    // 128 k x 128 c   [k][c]

    const int tid = threadIdx.x;
    const size_t row0 = (size_t)blockIdx.x * 256;
    const int coff = blockIdx.y * 128;
    W += coff;
    C += coff;
    if (bias) bias += coff;

    // Ws: 4096 float4s
    #pragma unroll
    for (int i = 0; i < 16; i++){
        int f  = tid + i*256;           // 0..4095
        int k  = f >> 5;
        int c4 = (f & 31) << 2;
        *(float4*)&Ws[k*128 + c4] = *(const float4*)(W + (size_t)k*ldw + c4);
    }
    // As: 256 rows x 128 k = 8192 float4s, transposed to [k][r]
    #pragma unroll
    for (int i = 0; i < 32; i++){
        int f  = tid + i*256;           // 0..8191
        int r  = f & 255;
        int k4 = (f >> 8) << 2;         // 0,4,...,124
        float4 v = *(const float4*)(A + (row0 + r)*Hq + k4);
        As[(k4+0)*256 + r] = v.x;
        As[(k4+1)*256 + r] = v.y;
        As[(k4+2)*256 + r] = v.z;
        As[(k4+3)*256 + r] = v.w;
    }
    __syncthreads();

    const int tx = tid & 7, ty = tid >> 3;   // tx: col group 0..7, ty: row group 0..31
    const int cb = tx*16, rb = ty*8;

    float acc[8][16];
    #pragma unroll
    for (int i=0;i<8;i++)
        #pragma unroll
        for (int j=0;j<16;j++) acc[i][j] = 0.f;

    #pragma unroll 2
    for (int k = 0; k < 128; k++){
        float a[8], b[16];
        *(float4*)&a[0]  = *(float4*)&As[k*256 + rb];
        *(float4*)&a[4]  = *(float4*)&As[k*256 + rb + 4];
        *(float4*)&b[0]  = *(float4*)&Ws[k*128 + cb];
        *(float4*)&b[4]  = *(float4*)&Ws[k*128 + cb + 4];
        *(float4*)&b[8]  = *(float4*)&Ws[k*128 + cb + 8];
        *(float4*)&b[12] = *(float4*)&Ws[k*128 + cb + 12];
        #pragma unroll
        for (int i=0;i<8;i++)
            #pragma unroll
            for (int j=0;j<16;j++)
                acc[i][j] = fmaf(a[i], b[j], acc[i][j]);
    }

    float bv[16];
    #pragma unroll
    for (int j=0;j<16;j++) bv[j] = bias ? bias[cb+j] : 0.f;

    #pragma unroll
    for (int i=0;i<8;i++){
        float* crow = C + (row0 + rb + i)*(size_t)ldc + cb;
        float o[16];
        #pragma unroll
        for (int j=0;j<16;j++){
            float v = __fadd_rn(acc[i][j], bv[j]);
            o[j] = act ? tanh_xla(v) : v;
        }
        #pragma unroll
        for (int q=0;q<4;q++)
            *(float4*)(crow + q*4) =
                make_float4(o[q*4+0],o[q*4+1],o[q*4+2],o[q*4+3]);
    }
}

// ---------------------------------------------------------------------------
// Batched aggregation: per (b,d): C[256][128] = A[256][256] @ B[256][128]
// R10-proven shape: 256 threads, thread tile 8x16. Bit-identical chains.
// ---------------------------------------------------------------------------
__global__ __launch_bounds__(256, 1)
void k_agg(const float* __restrict__ adj,
           const float* __restrict__ tmp,
           float* __restrict__ agg)
{
    extern __shared__ float smem[];
    float* Bs  = smem;             // 256*128   [t][h]
    float* Ast = smem + 256*128;   // 16*256    [kk][s]

    const int bd = blockIdx.x;
    const float* A  = adj + (size_t)bd*Sq*Sq;
    const float* Bm = tmp + (size_t)bd*Sq*Hq;
    float*       Cm = agg + (size_t)bd*Sq*Hq;
    const int tid = threadIdx.x;

    #pragma unroll
    for (int i = 0; i < 32; i++){
        int f = tid + i*256;  // 0..8191 float4s
        ((float4*)Bs)[f] = ((const float4*)Bm)[f];
    }

    const int hx = tid & 7, sy = tid >> 3;
    const int hb = hx*16, sb = sy*8;

    float acc[8][16];
    #pragma unroll
    for (int i=0;i<8;i++)
        #pragma unroll
        for (int j=0;j<16;j++) acc[i][j] = 0.f;

    for (int k0 = 0; k0 < 256; k0 += 16){
        __syncthreads();
        {
            const float4* src = (const float4*)(A + (size_t)tid*Sq + k0);
            #pragma unroll
            for (int q=0;q<4;q++){
                float4 v = src[q];
                Ast[(q*4+0)*256 + tid] = v.x;
                Ast[(q*4+1)*256 + tid] = v.y;
                Ast[(q*4+2)*256 + tid] = v.z;
                Ast[(q*4+3)*256 + tid] = v.w;
            }
        }
        __syncthreads();
        #pragma unroll
        for (int kk = 0; kk < 16; kk++){
            const int k = k0 + kk;
            float a[8], b[16];
            *(float4*)&a[0]  = *(float4*)&Ast[kk*256 + sb];
            *(float4*)&a[4]  = *(float4*)&Ast[kk*256 + sb + 4];
            *(float4*)&b[0]  = *(float4*)&Bs[k*128 + hb];
            *(float4*)&b[4]  = *(float4*)&Bs[k*128 + hb + 4];
            *(float4*)&b[8]  = *(float4*)&Bs[k*128 + hb + 8];
            *(float4*)&b[12] = *(float4*)&Bs[k*128 + hb + 12];
            #pragma unroll
            for (int i=0;i<8;i++)
                #pragma unroll
                for (int j=0;j<16;j++)
                    acc[i][j] = fmaf(a[i], b[j], acc[i][j]);
        }
    }

    #pragma unroll
    for (int i=0;i<8;i++){
        float* crow = Cm + (size_t)(sb + i)*Hq + hb;
        #pragma unroll
        for (int q=0;q<4;q++)
            *(float4*)(crow + q*4) =
                make_float4(acc[i][q*4+0],acc[i][q*4+1],acc[i][q*4+2],acc[i][q*4+3]);
    }
}

// ---------------------------------------------------------------------------
// GRU elementwise combine — FROZEN numerics (unfused; poly tanh; Cephes exp).
// ---------------------------------------------------------------------------
__device__ __forceinline__ float gru1(float ir,float iz,float inn,
                                      float hr,float hz,float hn,float h){
    float r  = sigmoid_xla(__fadd_rn(ir, hr));
    float z  = sigmoid_xla(__fadd_rn(iz, hz));
    float rhn = __fmul_rn(r, hn);
    float ng  = tanh_xla(__fadd_rn(inn, rhn));
    float omz = __fsub_rn(1.f, z);
    float t0  = __fmul_rn(omz, ng);
    float t1  = __fmul_rn(z, h);
    return __fadd_rn(t0, t1);
}

__global__ void k_gru(const float* __restrict__ gi,
                      const float* __restrict__ gh,
                      float* __restrict__ node)
{
    size_t t = (size_t)blockIdx.x*blockDim.x + threadIdx.x;  // NROW*32
    size_t n = t >> 5; int c = (int)(t & 31) << 2;
    const float* gin = gi + n*H3 + c;
    const float* ghn = gh + n*H3 + c;
    float* hp = node + n*Hq + c;
    float4 ir  = *(const float4*)(gin);
    float4 iz  = *(const float4*)(gin + 128);
    float4 inn = *(const float4*)(gin + 256);
    float4 hr  = *(const float4*)(ghn);
    float4 hz  = *(const float4*)(ghn + 128);
    float4 hn  = *(const float4*)(ghn + 256);
    float4 h   = *(float4*)hp;
    float4 o;
    o.x = gru1(ir.x,iz.x,inn.x,hr.x,hz.x,hn.x,h.x);
    o.y = gru1(ir.y,iz.y,inn.y,hr.y,hz.y,hn.y,h.y);
    o.z = gru1(ir.z,iz.z,inn.z,hr.z,hz.z,hn.z,h.z);
    o.w = gru1(ir.w,iz.w,inn.w,hr.w,hz.w,hn.w,h.w);
    *(float4*)hp = o;
}

// ---------------------------------------------------------------------------
// Final: out[n] = tanh(dot(t2[n], w3) + b3), one warp per row
// ---------------------------------------------------------------------------
__global__ void k_final(const float* __restrict__ t2,
                        const float* __restrict__ w3,
                        const float* __restrict__ b3,
                        float* __restrict__ out)
{
    size_t row = ((size_t)blockIdx.x*blockDim.x + threadIdx.x) >> 5;
    int lane = threadIdx.x & 31;
    const float* a = t2 + row*Hq + lane*4;
    const float* w = w3 + lane*4;
    float p = 0.f;
    #pragma unroll
    for (int q=0;q<4;q++) p = fmaf(a[q], w[q], p);
    #pragma unroll
    for (int o = 16; o; o >>= 1) p = __fadd_rn(p, __shfl_xor_sync(0xFFFFFFFFu, p, o));
    if (lane == 0) out[row] = tanh_xla(__fadd_rn(p, b3[0]));
}

// ---------------------------------------------------------------------------
extern "C" void kernel_launch(void* const* d_in, const int* in_sizes, int n_in,
                              void* d_out, int out_size)
{
    const int*   input_var = (const int*)  d_in[0];
    const float* adjacency = (const float*)d_in[1];
    const float* embed     = (const float*)d_in[2];
    const float* gnn_w     = (const float*)d_in[3];
    const float* gnn_b     = (const float*)d_in[4];
    const float* w_ih      = (const float*)d_in[5];
    const float* w_hh      = (const float*)d_in[6];
    const float* b_ih      = (const float*)d_in[7];
    const float* b_hh      = (const float*)d_in[8];
    const float* mlp_w1    = (const float*)d_in[9];
    const float* mlp_b1    = (const float*)d_in[10];
    const float* mlp_w2    = (const float*)d_in[11];
    const float* mlp_b2    = (const float*)d_in[12];
    const float* mlp_w3    = (const float*)d_in[13];
    const float* mlp_b3    = (const float*)d_in[14];
    float* out = (float*)d_out;

    float *node,*tmp,*agg,*gi,*gh,*wiht,*whht;
    cudaGetSymbolAddress((void**)&node, g_node);
    cudaGetSymbolAddress((void**)&tmp,  g_tmp);
    cudaGetSymbolAddress((void**)&agg,  g_agg);
    cudaGetSymbolAddress((void**)&gi,   g_gi);
    cudaGetSymbolAddress((void**)&gh,   g_gh);
    cudaGetSymbolAddress((void**)&wiht, g_wiht);
    cudaGetSymbolAddress((void**)&whht, g_whht);

    const int GEMM_SMEM = (128*256 + 128*128)*sizeof(float); // 196608
    const int AGG_SMEM  = (256*128 + 16*256)*sizeof(float);  // 147456
    cudaFuncSetAttribute(k_gemm, cudaFuncAttributeMaxDynamicSharedMemorySize, GEMM_SMEM);
    cudaFuncSetAttribute(k_agg,  cudaFuncAttributeMaxDynamicSharedMemorySize, AGG_SMEM);

    k_transpose<<<(H3*Hq + 255)/256, 256>>>(w_ih, wiht);
    k_transpose<<<(H3*Hq + 255)/256, 256>>>(w_hh, whht);
    k_gather<<<NROW*32/256, 256>>>(input_var, embed, node);

    for (int it = 0; it < NLOOP; it++){
        // tmp = node @ gnn_w + gnn_b
        k_gemm<<<dim3(NROW/256,1), 256, GEMM_SMEM>>>(node, gnn_w, 128, gnn_b, tmp, 128, 0);
        // agg[b,d] = adjacency[b,d] @ tmp[b,d]
        k_agg<<<BDq, 256, AGG_SMEM>>>(adjacency, tmp, agg);
        // gi = agg @ w_ih^T + b_ih ; gh = node @ w_hh^T + b_hh  (3 col chunks via gridDim.y)
        k_gemm<<<dim3(NROW/256,3), 256, GEMM_SMEM>>>(agg,  wiht, H3, b_ih, gi, H3, 0);
        k_gemm<<<dim3(NROW/256,3), 256, GEMM_SMEM>>>(node, whht, H3, b_hh, gh, H3, 0);
        k_gru<<<NROW*32/256, 256>>>(gi, gh, node);
    }

    // MLP head
    k_gemm<<<dim3(NROW/256,1), 256, GEMM_SMEM>>>(node, mlp_w1, 128, mlp_b1, tmp, 128, 1);
    k_gemm<<<dim3(NROW/256,1), 256, GEMM_SMEM>>>(tmp,  mlp_w2, 128, mlp_b2, agg, 128, 1);
    k_final<<<NROW/8, 256>>>(agg, mlp_w3, mlp_b3, out);
}

// round 13
// speedup vs baseline: 1.4366x; 1.4366x over previous
#include <cuda_runtime.h>
#include <math.h>

// Problem constants
#define Bq 16
#define Dq 64
#define Sq 256
#define Hq 128
#define H3 384
#define NROW (Bq*Dq*Sq)   // 262144
#define BDq (Bq*Dq)       // 1024
#define NLOOP 10

// Scratch (device globals: allocation-free rule)
__device__ float g_node[NROW*Hq];
__device__ float g_tmp [NROW*Hq];
__device__ float g_agg [NROW*Hq];
__device__ float g_gi  [NROW*H3];
__device__ float g_gh  [NROW*H3];
__device__ float g_wiht[Hq*H3];
__device__ float g_whht[Hq*H3];

// ---------------------------------------------------------------------------
// FROZEN NUMERICS (R10-verified): XLA EmitFastTanh, unfused mul/add.
// ---------------------------------------------------------------------------
__device__ __forceinline__ float tanh_xla(float x){
    float ax = fabsf(x);
    if (ax < 0.0004f) return x;
    float xc = fminf(fmaxf(x, -7.90531110763549805f), 7.90531110763549805f);
    float a  = __fmul_rn(xc, xc);
    float p = __fadd_rn(__fmul_rn(a, -2.76076847742355e-16f), 2.00018790482477e-13f);
    p = __fadd_rn(__fmul_rn(a, p), -8.60467152213735e-11f);
    p = __fadd_rn(__fmul_rn(a, p),  5.12229709037114e-08f);
    p = __fadd_rn(__fmul_rn(a, p),  1.48572235717979e-05f);
    p = __fadd_rn(__fmul_rn(a, p),  6.37261928875436e-04f);
    p = __fadd_rn(__fmul_rn(a, p),  4.89352455891786e-03f);
    float num = __fmul_rn(xc, p);
    float q = __fadd_rn(__fmul_rn(a, 1.19825839466702e-06f), 1.18534705686654e-04f);
    q = __fadd_rn(__fmul_rn(a, q), 2.26843463243900e-03f);
    q = __fadd_rn(__fmul_rn(a, q), 4.89352518554385e-03f);
    return __fdiv_rn(num, q);
}

// FROZEN: Cephes/Eigen f32 exp, unfused.
__device__ __forceinline__ float exp_cephes(float x){
    x = fminf(x,  88.3762626647950f);
    x = fmaxf(x, -88.3762626647949f);
    float m = floorf(__fadd_rn(__fmul_rn(x, 1.44269504088896341f), 0.5f));
    float r = __fsub_rn(x, __fmul_rn(m, 0.693359375f));
    r = __fsub_rn(r, __fmul_rn(m, -2.12194440e-4f));
    float z = __fmul_rn(r, r);
    float y = 1.9875691500e-4f;
    y = __fadd_rn(__fmul_rn(y, r), 1.3981999507e-3f);
    y = __fadd_rn(__fmul_rn(y, r), 8.3334519073e-3f);
    y = __fadd_rn(__fmul_rn(y, r), 4.1665795894e-2f);
    y = __fadd_rn(__fmul_rn(y, r), 1.6666665459e-1f);
    y = __fadd_rn(__fmul_rn(y, r), 5.0000001201e-1f);
    y = __fadd_rn(__fmul_rn(y, z), r);
    y = __fadd_rn(y, 1.0f);
    int mi = (int)m;
    float s = __int_as_float((mi + 127) << 23);
    return __fmul_rn(y, s);
}

__device__ __forceinline__ float sigmoid_xla(float x){
    float e = exp_cephes(-x);
    return __fdiv_rn(1.f, __fadd_rn(1.f, e));
}

// ---------------------------------------------------------------------------
// Embedding gather: node[n][:] = embed[idx[n]][:]
// ---------------------------------------------------------------------------
__global__ void k_gather(const int* __restrict__ idx,
                         const float* __restrict__ embed,
                         float* __restrict__ node)
{
    size_t t = (size_t)blockIdx.x*blockDim.x + threadIdx.x;   // NROW*32 threads
    size_t n = t >> 5; int c = (int)(t & 31) << 2;
    float4 v = *(const float4*)(embed + (size_t)idx[n]*Hq + c);
    *(float4*)(node + n*Hq + c) = v;
}

// ---------------------------------------------------------------------------
// Weight transpose: wt[k][j] = w[j][k], w is [H3][Hq]
// ---------------------------------------------------------------------------
__global__ void k_transpose(const float* __restrict__ w, float* __restrict__ wt)
{
    int t = blockIdx.x*blockDim.x + threadIdx.x;
    if (t < H3*Hq){ int j = t / Hq, k = t % Hq; wt[k*H3 + j] = w[t]; }
}

// ---------------------------------------------------------------------------
// GEMM: C[row][c] = sum_k A[row][k]*W[k*ldw+c] (+bias, opt tanh)
// Sequential-k FMA chain per output — bit-identical to R10.
// Block: 512 threads, 256 rows x 128 cols, thread tile 8x8 (1.0 B/FMA),
// 16 warps/SM. smem: As[128][256] (128KB) + Ws[128][128] (64KB) = 192KB.
// blockIdx.y = 128-column chunk (W/bias/C offset by y*128).
// ---------------------------------------------------------------------------
__global__ __launch_bounds__(512, 1)
void k_gemm(const float* __restrict__ A,
            const float* __restrict__ W, int ldw,
            const float* __restrict__ bias,
            float* __restrict__ C, int ldc, int act)
{
    extern __shared__ float smem[];
    float* As = smem;              // 128 k x 256 r   [k][r]
    float* Ws = smem + 128*256;    // 128 k x 128 c   [k][c]

    const int tid = threadIdx.x;
    const size_t row0 = (size_t)blockIdx.x * 256;
    const int coff = blockIdx.y * 128;
    W += coff;
    C += coff;
    if (bias) bias += coff;

    // Ws: 4096 float4s
    #pragma unroll
    for (int i = 0; i < 8; i++){
        int f  = tid + i*512;           // 0..4095
        int k  = f >> 5;
        int c4 = (f & 31) << 2;
        *(float4*)&Ws[k*128 + c4] = *(const float4*)(W + (size_t)k*ldw + c4);
    }
    // As: 256 rows x 128 k = 8192 float4s, transposed to [k][r]
    #pragma unroll
    for (int i = 0; i < 16; i++){
        int f  = tid + i*512;           // 0..8191
        int r  = f & 255;
        int k4 = (f >> 8) << 2;         // 0,4,...,124
        float4 v = *(const float4*)(A + (row0 + r)*Hq + k4);
        As[(k4+0)*256 + r] = v.x;
        As[(k4+1)*256 + r] = v.y;
        As[(k4+2)*256 + r] = v.z;
        As[(k4+3)*256 + r] = v.w;
    }
    __syncthreads();

    const int tx = tid & 15, ty = tid >> 4;   // tx: col group 0..15, ty: row group 0..31
    const int cb = tx*8, rb = ty*8;

    float acc[8][8];
    #pragma unroll
    for (int i=0;i<8;i++)
        #pragma unroll
        for (int j=0;j<8;j++) acc[i][j] = 0.f;

    #pragma unroll 4
    for (int k = 0; k < 128; k++){
        float a[8], b[8];
        *(float4*)&a[0] = *(float4*)&As[k*256 + rb];
        *(float4*)&a[4] = *(float4*)&As[k*256 + rb + 4];
        *(float4*)&b[0] = *(float4*)&Ws[k*128 + cb];
        *(float4*)&b[4] = *(float4*)&Ws[k*128 + cb + 4];
        #pragma unroll
        for (int i=0;i<8;i++)
            #pragma unroll
            for (int j=0;j<8;j++)
                acc[i][j] = fmaf(a[i], b[j], acc[i][j]);
    }

    float bv[8];
    #pragma unroll
    for (int j=0;j<8;j++) bv[j] = bias ? bias[cb+j] : 0.f;

    #pragma unroll
    for (int i=0;i<8;i++){
        float* crow = C + (row0 + rb + i)*(size_t)ldc + cb;
        float o[8];
        #pragma unroll
        for (int j=0;j<8;j++){
            float v = __fadd_rn(acc[i][j], bv[j]);
            o[j] = act ? tanh_xla(v) : v;
        }
        *(float4*)(crow)   = make_float4(o[0],o[1],o[2],o[3]);
        *(float4*)(crow+4) = make_float4(o[4],o[5],o[6],o[7]);
    }
}

// ---------------------------------------------------------------------------
// Batched aggregation: per (b,d): C[256][128] = A[256][256] @ B[256][128]
// R11-proven shape: 512 threads, thread tile 8x8. Bit-identical chains.
// ---------------------------------------------------------------------------
__global__ __launch_bounds__(512, 1)
void k_agg(const float* __restrict__ adj,
           const float* __restrict__ tmp,
           float* __restrict__ agg)
{
    extern __shared__ float smem[];
    float* Bs  = smem;             // 256*128   [t][h]
    float* Ast = smem + 256*128;   // 16*256    [kk][s]

    const int bd = blockIdx.x;
    const float* A  = adj + (size_t)bd*Sq*Sq;
    const float* Bm = tmp + (size_t)bd*Sq*Hq;
    float*       Cm = agg + (size_t)bd*Sq*Hq;
    const int tid = threadIdx.x;

    #pragma unroll
    for (int i = 0; i < 16; i++){
        int f = tid + i*512;  // 0..8191 float4s
        ((float4*)Bs)[f] = ((const float4*)Bm)[f];
    }

    const int hx = tid & 15, sy = tid >> 4;
    const int cb = hx*8, sb = sy*8;

    float acc[8][8];
    #pragma unroll
    for (int i=0;i<8;i++)
        #pragma unroll
        for (int j=0;j<8;j++) acc[i][j] = 0.f;

    for (int k0 = 0; k0 < 256; k0 += 16){
        __syncthreads();
        // Ast[kk][s] = A[s][k0+kk]; 512 threads: s = tid&255, k-half = (tid>>8)*8
        {
            int r  = tid & 255;
            int kh = (tid >> 8) << 3;
            const float* src = A + (size_t)r*Sq + k0 + kh;
            float4 v0 = *(const float4*)(src);
            float4 v1 = *(const float4*)(src + 4);
            Ast[(kh+0)*256 + r] = v0.x;
            Ast[(kh+1)*256 + r] = v0.y;
            Ast[(kh+2)*256 + r] = v0.z;
            Ast[(kh+3)*256 + r] = v0.w;
            Ast[(kh+4)*256 + r] = v1.x;
            Ast[(kh+5)*256 + r] = v1.y;
            Ast[(kh+6)*256 + r] = v1.z;
            Ast[(kh+7)*256 + r] = v1.w;
        }
        __syncthreads();
        #pragma unroll
        for (int kk = 0; kk < 16; kk++){
            const int k = k0 + kk;
            float a[8], b[8];
            *(float4*)&a[0] = *(float4*)&Ast[kk*256 + sb];
            *(float4*)&a[4] = *(float4*)&Ast[kk*256 + sb + 4];
            *(float4*)&b[0] = *(float4*)&Bs[k*128 + cb];
            *(float4*)&b[4] = *(float4*)&Bs[k*128 + cb + 4];
            #pragma unroll
            for (int i=0;i<8;i++)
                #pragma unroll
                for (int j=0;j<8;j++)
                    acc[i][j] = fmaf(a[i], b[j], acc[i][j]);
        }
    }

    #pragma unroll
    for (int i=0;i<8;i++){
        float* crow = Cm + (size_t)(sb + i)*Hq + cb;
        *(float4*)(crow)   = make_float4(acc[i][0],acc[i][1],acc[i][2],acc[i][3]);
        *(float4*)(crow+4) = make_float4(acc[i][4],acc[i][5],acc[i][6],acc[i][7]);
    }
}

// ---------------------------------------------------------------------------
// GRU elementwise combine — FROZEN numerics (unfused; poly tanh; Cephes exp).
// ---------------------------------------------------------------------------
__device__ __forceinline__ float gru1(float ir,float iz,float inn,
                                      float hr,float hz,float hn,float h){
    float r  = sigmoid_xla(__fadd_rn(ir, hr));
    float z  = sigmoid_xla(__fadd_rn(iz, hz));
    float rhn = __fmul_rn(r, hn);
    float ng  = tanh_xla(__fadd_rn(inn, rhn));
    float omz = __fsub_rn(1.f, z);
    float t0  = __fmul_rn(omz, ng);
    float t1  = __fmul_rn(z, h);
    return __fadd_rn(t0, t1);
}

__global__ void k_gru(const float* __restrict__ gi,
                      const float* __restrict__ gh,
                      float* __restrict__ node)
{
    size_t t = (size_t)blockIdx.x*blockDim.x + threadIdx.x;  // NROW*32
    size_t n = t >> 5; int c = (int)(t & 31) << 2;
    const float* gin = gi + n*H3 + c;
    const float* ghn = gh + n*H3 + c;
    float* hp = node + n*Hq + c;
    float4 ir  = *(const float4*)(gin);
    float4 iz  = *(const float4*)(gin + 128);
    float4 inn = *(const float4*)(gin + 256);
    float4 hr  = *(const float4*)(ghn);
    float4 hz  = *(const float4*)(ghn + 128);
    float4 hn  = *(const float4*)(ghn + 256);
    float4 h   = *(float4*)hp;
    float4 o;
    o.x = gru1(ir.x,iz.x,inn.x,hr.x,hz.x,hn.x,h.x);
    o.y = gru1(ir.y,iz.y,inn.y,hr.y,hz.y,hn.y,h.y);
    o.z = gru1(ir.z,iz.z,inn.z,hr.z,hz.z,hn.z,h.z);
    o.w = gru1(ir.w,iz.w,inn.w,hr.w,hz.w,hn.w,h.w);
    *(float4*)hp = o;
}

// ---------------------------------------------------------------------------
// Final: out[n] = tanh(dot(t2[n], w3) + b3), one warp per row
// ---------------------------------------------------------------------------
__global__ void k_final(const float* __restrict__ t2,
                        const float* __restrict__ w3,
                        const float* __restrict__ b3,
                        float* __restrict__ out)
{
    size_t row = ((size_t)blockIdx.x*blockDim.x + threadIdx.x) >> 5;
    int lane = threadIdx.x & 31;
    const float* a = t2 + row*Hq + lane*4;
    const float* w = w3 + lane*4;
    float p = 0.f;
    #pragma unroll
    for (int q=0;q<4;q++) p = fmaf(a[q], w[q], p);
    #pragma unroll
    for (int o = 16; o; o >>= 1) p = __fadd_rn(p, __shfl_xor_sync(0xFFFFFFFFu, p, o));
    if (lane == 0) out[row] = tanh_xla(__fadd_rn(p, b3[0]));
}

// ---------------------------------------------------------------------------
extern "C" void kernel_launch(void* const* d_in, const int* in_sizes, int n_in,
                              void* d_out, int out_size)
{
    const int*   input_var = (const int*)  d_in[0];
    const float* adjacency = (const float*)d_in[1];
    const float* embed     = (const float*)d_in[2];
    const float* gnn_w     = (const float*)d_in[3];
    const float* gnn_b     = (const float*)d_in[4];
    const float* w_ih      = (const float*)d_in[5];
    const float* w_hh      = (const float*)d_in[6];
    const float* b_ih      = (const float*)d_in[7];
    const float* b_hh      = (const float*)d_in[8];
    const float* mlp_w1    = (const float*)d_in[9];
    const float* mlp_b1    = (const float*)d_in[10];
    const float* mlp_w2    = (const float*)d_in[11];
    const float* mlp_b2    = (const float*)d_in[12];
    const float* mlp_w3    = (const float*)d_in[13];
    const float* mlp_b3    = (const float*)d_in[14];
    float* out = (float*)d_out;

    float *node,*tmp,*agg,*gi,*gh,*wiht,*whht;
    cudaGetSymbolAddress((void**)&node, g_node);
    cudaGetSymbolAddress((void**)&tmp,  g_tmp);
    cudaGetSymbolAddress((void**)&agg,  g_agg);
    cudaGetSymbolAddress((void**)&gi,   g_gi);
    cudaGetSymbolAddress((void**)&gh,   g_gh);
    cudaGetSymbolAddress((void**)&wiht, g_wiht);
    cudaGetSymbolAddress((void**)&whht, g_whht);

    const int GEMM_SMEM = (128*256 + 128*128)*sizeof(float); // 196608
    const int AGG_SMEM  = (256*128 + 16*256)*sizeof(float);  // 147456
    cudaFuncSetAttribute(k_gemm, cudaFuncAttributeMaxDynamicSharedMemorySize, GEMM_SMEM);
    cudaFuncSetAttribute(k_agg,  cudaFuncAttributeMaxDynamicSharedMemorySize, AGG_SMEM);

    k_transpose<<<(H3*Hq + 255)/256, 256>>>(w_ih, wiht);
    k_transpose<<<(H3*Hq + 255)/256, 256>>>(w_hh, whht);
    k_gather<<<NROW*32/256, 256>>>(input_var, embed, node);

    for (int it = 0; it < NLOOP; it++){
        // tmp = node @ gnn_w + gnn_b
        k_gemm<<<dim3(NROW/256,1), 512, GEMM_SMEM>>>(node, gnn_w, 128, gnn_b, tmp, 128, 0);
        // agg[b,d] = adjacency[b,d] @ tmp[b,d]
        k_agg<<<BDq, 512, AGG_SMEM>>>(adjacency, tmp, agg);
        // gi = agg @ w_ih^T + b_ih ; gh = node @ w_hh^T + b_hh  (3 col chunks via gridDim.y)
        k_gemm<<<dim3(NROW/256,3), 512, GEMM_SMEM>>>(agg,  wiht, H3, b_ih, gi, H3, 0);
        k_gemm<<<dim3(NROW/256,3), 512, GEMM_SMEM>>>(node, whht, H3, b_hh, gh, H3, 0);
        k_gru<<<NROW*32/256, 256>>>(gi, gh, node);
    }

    // MLP head
    k_gemm<<<dim3(NROW/256,1), 512, GEMM_SMEM>>>(node, mlp_w1, 128, mlp_b1, tmp, 128, 1);
    k_gemm<<<dim3(NROW/256,1), 512, GEMM_SMEM>>>(tmp,  mlp_w2, 128, mlp_b2, agg, 128, 1);
    k_final<<<NROW/8, 256>>>(agg, mlp_w3, mlp_b3, out);
}

// round 14
// speedup vs baseline: 1.4584x; 1.0152x over previous
#include <cuda_runtime.h>
#include <math.h>

// Problem constants
#define Bq 16
#define Dq 64
#define Sq 256
#define Hq 128
#define H3 384
#define NROW (Bq*Dq*Sq)   // 262144
#define BDq (Bq*Dq)       // 1024
#define NLOOP 10

// Scratch (device globals: allocation-free rule)
__device__ float g_node[NROW*Hq];
__device__ float g_tmp [NROW*Hq];
__device__ float g_agg [NROW*Hq];
__device__ float g_gi  [NROW*H3];
__device__ float g_gh  [NROW*H3];
__device__ float g_wiht[Hq*H3];
__device__ float g_whht[Hq*H3];

// ---------------------------------------------------------------------------
// Packed fp32x2 FMA (sm_103a FFMA2): two independent IEEE-rn fp32 FMAs per
// instruction. Per-half rounding identical to scalar fmaf -> bit-identical
// accumulation chains at 2x pipe throughput.
// ---------------------------------------------------------------------------
__device__ __forceinline__ unsigned long long splat2(float x){
    unsigned long long r;
    unsigned u = __float_as_uint(x);
    asm("mov.b64 %0, {%1, %1};" : "=l"(r) : "r"(u));
    return r;
}
__device__ __forceinline__ unsigned long long fma2(unsigned long long a,
                                                   unsigned long long b,
                                                   unsigned long long c){
    unsigned long long d;
    asm("fma.rn.f32x2 %0, %1, %2, %3;" : "=l"(d) : "l"(a), "l"(b), "l"(c));
    return d;
}
__device__ __forceinline__ float2 unpack2(unsigned long long p){
    unsigned lo, hi;
    asm("mov.b64 {%0, %1}, %2;" : "=r"(lo), "=r"(hi) : "l"(p));
    return make_float2(__uint_as_float(lo), __uint_as_float(hi));
}

// ---------------------------------------------------------------------------
// FROZEN NUMERICS (R10-verified): XLA EmitFastTanh, unfused mul/add.
// ---------------------------------------------------------------------------
__device__ __forceinline__ float tanh_xla(float x){
    float ax = fabsf(x);
    if (ax < 0.0004f) return x;
    float xc = fminf(fmaxf(x, -7.90531110763549805f), 7.90531110763549805f);
    float a  = __fmul_rn(xc, xc);
    float p = __fadd_rn(__fmul_rn(a, -2.76076847742355e-16f), 2.00018790482477e-13f);
    p = __fadd_rn(__fmul_rn(a, p), -8.60467152213735e-11f);
    p = __fadd_rn(__fmul_rn(a, p),  5.12229709037114e-08f);
    p = __fadd_rn(__fmul_rn(a, p),  1.48572235717979e-05f);
    p = __fadd_rn(__fmul_rn(a, p),  6.37261928875436e-04f);
    p = __fadd_rn(__fmul_rn(a, p),  4.89352455891786e-03f);
    float num = __fmul_rn(xc, p);
    float q = __fadd_rn(__fmul_rn(a, 1.19825839466702e-06f), 1.18534705686654e-04f);
    q = __fadd_rn(__fmul_rn(a, q), 2.26843463243900e-03f);
    q = __fadd_rn(__fmul_rn(a, q), 4.89352518554385e-03f);
    return __fdiv_rn(num, q);
}

// FROZEN: Cephes/Eigen f32 exp, unfused.
__device__ __forceinline__ float exp_cephes(float x){
    x = fminf(x,  88.3762626647950f);
    x = fmaxf(x, -88.3762626647949f);
    float m = floorf(__fadd_rn(__fmul_rn(x, 1.44269504088896341f), 0.5f));
    float r = __fsub_rn(x, __fmul_rn(m, 0.693359375f));
    r = __fsub_rn(r, __fmul_rn(m, -2.12194440e-4f));
    float z = __fmul_rn(r, r);
    float y = 1.9875691500e-4f;
    y = __fadd_rn(__fmul_rn(y, r), 1.3981999507e-3f);
    y = __fadd_rn(__fmul_rn(y, r), 8.3334519073e-3f);
    y = __fadd_rn(__fmul_rn(y, r), 4.1665795894e-2f);
    y = __fadd_rn(__fmul_rn(y, r), 1.6666665459e-1f);
    y = __fadd_rn(__fmul_rn(y, r), 5.0000001201e-1f);
    y = __fadd_rn(__fmul_rn(y, z), r);
    y = __fadd_rn(y, 1.0f);
    int mi = (int)m;
    float s = __int_as_float((mi + 127) << 23);
    return __fmul_rn(y, s);
}

__device__ __forceinline__ float sigmoid_xla(float x){
    float e = exp_cephes(-x);
    return __fdiv_rn(1.f, __fadd_rn(1.f, e));
}

// ---------------------------------------------------------------------------
// Embedding gather: node[n][:] = embed[idx[n]][:]
// ---------------------------------------------------------------------------
__global__ void k_gather(const int* __restrict__ idx,
                         const float* __restrict__ embed,
                         float* __restrict__ node)
{
    size_t t = (size_t)blockIdx.x*blockDim.x + threadIdx.x;   // NROW*32 threads
    size_t n = t >> 5; int c = (int)(t & 31) << 2;
    float4 v = *(const float4*)(embed + (size_t)idx[n]*Hq + c);
    *(float4*)(node + n*Hq + c) = v;
}

// ---------------------------------------------------------------------------
// Weight transpose: wt[k][j] = w[j][k], w is [H3][Hq]
// ---------------------------------------------------------------------------
__global__ void k_transpose(const float* __restrict__ w, float* __restrict__ wt)
{
    int t = blockIdx.x*blockDim.x + threadIdx.x;
    if (t < H3*Hq){ int j = t / Hq, k = t % Hq; wt[k*H3 + j] = w[t]; }
}

// ---------------------------------------------------------------------------
// GEMM: C[row][c] = sum_k A[row][k]*W[k*ldw+c] (+bias, opt tanh)
// Inner loop in packed f32x2 (bit-identical per-half chains).
// Block: 512 threads, 256 rows x 128 cols, thread tile 8x8.
// smem: As[128][256] (128KB) + Ws[128][128] (64KB) = 192KB.
// blockIdx.y = 128-column chunk (W/bias/C offset by y*128).
// ---------------------------------------------------------------------------
__global__ __launch_bounds__(512, 1)
void k_gemm(const float* __restrict__ A,
            const float* __restrict__ W, int ldw,
            const float* __restrict__ bias,
            float* __restrict__ C, int ldc, int act)
{
    extern __shared__ float smem[];
    float* As = smem;              // 128 k x 256 r   [k][r]
    float* Ws = smem + 128*256;    // 128 k x 128 c   [k][c]

    const int tid = threadIdx.x;
    const size_t row0 = (size_t)blockIdx.x * 256;
    const int coff = blockIdx.y * 128;
    W += coff;
    C += coff;
    if (bias) bias += coff;

    // Ws: 4096 float4s
    #pragma unroll
    for (int i = 0; i < 8; i++){
        int f  = tid + i*512;           // 0..4095
        int k  = f >> 5;
        int c4 = (f & 31) << 2;
        *(float4*)&Ws[k*128 + c4] = *(const float4*)(W + (size_t)k*ldw + c4);
    }
    // As: 256 rows x 128 k = 8192 float4s, transposed to [k][r]
    #pragma unroll
    for (int i = 0; i < 16; i++){
        int f  = tid + i*512;           // 0..8191
        int r  = f & 255;
        int k4 = (f >> 8) << 2;         // 0,4,...,124
        float4 v = *(const float4*)(A + (row0 + r)*Hq + k4);
        As[(k4+0)*256 + r] = v.x;
        As[(k4+1)*256 + r] = v.y;
        As[(k4+2)*256 + r] = v.z;
        As[(k4+3)*256 + r] = v.w;
    }
    __syncthreads();

    const int tx = tid & 15, ty = tid >> 4;   // tx: col group 0..15, ty: row group 0..31
    const int cb = tx*8, rb = ty*8;

    unsigned long long acc[8][4];             // 8 rows x 4 col-pairs
    #pragma unroll
    for (int i=0;i<8;i++)
        #pragma unroll
        for (int j=0;j<4;j++) acc[i][j] = 0ULL;

    #pragma unroll 4
    for (int k = 0; k < 128; k++){
        float a[8];
        *(float4*)&a[0] = *(float4*)&As[k*256 + rb];
        *(float4*)&a[4] = *(float4*)&As[k*256 + rb + 4];
        // b column pairs straight from smem as 64-bit lanes
        ulonglong2 b01 = *(ulonglong2*)&Ws[k*128 + cb];
        ulonglong2 b23 = *(ulonglong2*)&Ws[k*128 + cb + 4];
        unsigned long long bp0 = b01.x, bp1 = b01.y, bp2 = b23.x, bp3 = b23.y;
        #pragma unroll
        for (int i=0;i<8;i++){
            unsigned long long ap = splat2(a[i]);
            acc[i][0] = fma2(ap, bp0, acc[i][0]);
            acc[i][1] = fma2(ap, bp1, acc[i][1]);
            acc[i][2] = fma2(ap, bp2, acc[i][2]);
            acc[i][3] = fma2(ap, bp3, acc[i][3]);
        }
    }

    float bv[8];
    #pragma unroll
    for (int j=0;j<8;j++) bv[j] = bias ? bias[cb+j] : 0.f;

    #pragma unroll
    for (int i=0;i<8;i++){
        float* crow = C + (row0 + rb + i)*(size_t)ldc + cb;
        float o[8];
        #pragma unroll
        for (int j=0;j<4;j++){
            float2 v2 = unpack2(acc[i][j]);
            float v0 = __fadd_rn(v2.x, bv[j*2+0]);
            float v1 = __fadd_rn(v2.y, bv[j*2+1]);
            o[j*2+0] = act ? tanh_xla(v0) : v0;
            o[j*2+1] = act ? tanh_xla(v1) : v1;
        }
        *(float4*)(crow)   = make_float4(o[0],o[1],o[2],o[3]);
        *(float4*)(crow+4) = make_float4(o[4],o[5],o[6],o[7]);
    }
}

// ---------------------------------------------------------------------------
// Batched aggregation: per (b,d): C[256][128] = A[256][256] @ B[256][128]
// R13 shape (512 threads, 8x8 tile); inner loop in packed f32x2.
// ---------------------------------------------------------------------------
__global__ __launch_bounds__(512, 1)
void k_agg(const float* __restrict__ adj,
           const float* __restrict__ tmp,
           float* __restrict__ agg)
{
    extern __shared__ float smem[];
    float* Bs  = smem;             // 256*128   [t][h]
    float* Ast = smem + 256*128;   // 16*256    [kk][s]

    const int bd = blockIdx.x;
    const float* A  = adj + (size_t)bd*Sq*Sq;
    const float* Bm = tmp + (size_t)bd*Sq*Hq;
    float*       Cm = agg + (size_t)bd*Sq*Hq;
    const int tid = threadIdx.x;

    #pragma unroll
    for (int i = 0; i < 16; i++){
        int f = tid + i*512;  // 0..8191 float4s
        ((float4*)Bs)[f] = ((const float4*)Bm)[f];
    }

    const int hx = tid & 15, sy = tid >> 4;
    const int cb = hx*8, sb = sy*8;

    unsigned long long acc[8][4];
    #pragma unroll
    for (int i=0;i<8;i++)
        #pragma unroll
        for (int j=0;j<4;j++) acc[i][j] = 0ULL;

    for (int k0 = 0; k0 < 256; k0 += 16){
        __syncthreads();
        // Ast[kk][s] = A[s][k0+kk]; 512 threads: s = tid&255, k-half = (tid>>8)*8
        {
            int r  = tid & 255;
            int kh = (tid >> 8) << 3;
            const float* src = A + (size_t)r*Sq + k0 + kh;
            float4 v0 = *(const float4*)(src);
            float4 v1 = *(const float4*)(src + 4);
            Ast[(kh+0)*256 + r] = v0.x;
            Ast[(kh+1)*256 + r] = v0.y;
            Ast[(kh+2)*256 + r] = v0.z;
            Ast[(kh+3)*256 + r] = v0.w;
            Ast[(kh+4)*256 + r] = v1.x;
            Ast[(kh+5)*256 + r] = v1.y;
            Ast[(kh+6)*256 + r] = v1.z;
            Ast[(kh+7)*256 + r] = v1.w;
        }
        __syncthreads();
        #pragma unroll
        for (int kk = 0; kk < 16; kk++){
            const int k = k0 + kk;
            float a[8];
            *(float4*)&a[0] = *(float4*)&Ast[kk*256 + sb];
            *(float4*)&a[4] = *(float4*)&Ast[kk*256 + sb + 4];
            ulonglong2 b01 = *(ulonglong2*)&Bs[k*128 + cb];
            ulonglong2 b23 = *(ulonglong2*)&Bs[k*128 + cb + 4];
            unsigned long long bp0 = b01.x, bp1 = b01.y, bp2 = b23.x, bp3 = b23.y;
            #pragma unroll
            for (int i=0;i<8;i++){
                unsigned long long ap = splat2(a[i]);
                acc[i][0] = fma2(ap, bp0, acc[i][0]);
                acc[i][1] = fma2(ap, bp1, acc[i][1]);
                acc[i][2] = fma2(ap, bp2, acc[i][2]);
                acc[i][3] = fma2(ap, bp3, acc[i][3]);
            }
        }
    }

    #pragma unroll
    for (int i=0;i<8;i++){
        float* crow = Cm + (size_t)(sb + i)*Hq + cb;
        float2 v0 = unpack2(acc[i][0]);
        float2 v1 = unpack2(acc[i][1]);
        float2 v2 = unpack2(acc[i][2]);
        float2 v3 = unpack2(acc[i][3]);
        *(float4*)(crow)   = make_float4(v0.x, v0.y, v1.x, v1.y);
        *(float4*)(crow+4) = make_float4(v2.x, v2.y, v3.x, v3.y);
    }
}

// ---------------------------------------------------------------------------
// GRU elementwise combine — FROZEN numerics (unfused; poly tanh; Cephes exp).
// ---------------------------------------------------------------------------
__device__ __forceinline__ float gru1(float ir,float iz,float inn,
                                      float hr,float hz,float hn,float h){
    float r  = sigmoid_xla(__fadd_rn(ir, hr));
    float z  = sigmoid_xla(__fadd_rn(iz, hz));
    float rhn = __fmul_rn(r, hn);
    float ng  = tanh_xla(__fadd_rn(inn, rhn));
    float omz = __fsub_rn(1.f, z);
    float t0  = __fmul_rn(omz, ng);
    float t1  = __fmul_rn(z, h);
    return __fadd_rn(t0, t1);
}

__global__ void k_gru(const float* __restrict__ gi,
                      const float* __restrict__ gh,
                      float* __restrict__ node)
{
    size_t t = (size_t)blockIdx.x*blockDim.x + threadIdx.x;  // NROW*32
    size_t n = t >> 5; int c = (int)(t & 31) << 2;
    const float* gin = gi + n*H3 + c;
    const float* ghn = gh + n*H3 + c;
    float* hp = node + n*Hq + c;
    float4 ir  = *(const float4*)(gin);
    float4 iz  = *(const float4*)(gin + 128);
    float4 inn = *(const float4*)(gin + 256);
    float4 hr  = *(const float4*)(ghn);
    float4 hz  = *(const float4*)(ghn + 128);
    float4 hn  = *(const float4*)(ghn + 256);
    float4 h   = *(float4*)hp;
    float4 o;
    o.x = gru1(ir.x,iz.x,inn.x,hr.x,hz.x,hn.x,h.x);
    o.y = gru1(ir.y,iz.y,inn.y,hr.y,hz.y,hn.y,h.y);
    o.z = gru1(ir.z,iz.z,inn.z,hr.z,hz.z,hn.z,h.z);
    o.w = gru1(ir.w,iz.w,inn.w,hr.w,hz.w,hn.w,h.w);
    *(float4*)hp = o;
}

// ---------------------------------------------------------------------------
// Final: out[n] = tanh(dot(t2[n], w3) + b3), one warp per row
// ---------------------------------------------------------------------------
__global__ void k_final(const float* __restrict__ t2,
                        const float* __restrict__ w3,
                        const float* __restrict__ b3,
                        float* __restrict__ out)
{
    size_t row = ((size_t)blockIdx.x*blockDim.x + threadIdx.x) >> 5;
    int lane = threadIdx.x & 31;
    const float* a = t2 + row*Hq + lane*4;
    const float* w = w3 + lane*4;
    float p = 0.f;
    #pragma unroll
    for (int q=0;q<4;q++) p = fmaf(a[q], w[q], p);
    #pragma unroll
    for (int o = 16; o; o >>= 1) p = __fadd_rn(p, __shfl_xor_sync(0xFFFFFFFFu, p, o));
    if (lane == 0) out[row] = tanh_xla(__fadd_rn(p, b3[0]));
}

// ---------------------------------------------------------------------------
extern "C" void kernel_launch(void* const* d_in, const int* in_sizes, int n_in,
                              void* d_out, int out_size)
{
    const int*   input_var = (const int*)  d_in[0];
    const float* adjacency = (const float*)d_in[1];
    const float* embed     = (const float*)d_in[2];
    const float* gnn_w     = (const float*)d_in[3];
    const float* gnn_b     = (const float*)d_in[4];
    const float* w_ih      = (const float*)d_in[5];
    const float* w_hh      = (const float*)d_in[6];
    const float* b_ih      = (const float*)d_in[7];
    const float* b_hh      = (const float*)d_in[8];
    const float* mlp_w1    = (const float*)d_in[9];
    const float* mlp_b1    = (const float*)d_in[10];
    const float* mlp_w2    = (const float*)d_in[11];
    const float* mlp_b2    = (const float*)d_in[12];
    const float* mlp_w3    = (const float*)d_in[13];
    const float* mlp_b3    = (const float*)d_in[14];
    float* out = (float*)d_out;

    float *node,*tmp,*agg,*gi,*gh,*wiht,*whht;
    cudaGetSymbolAddress((void**)&node, g_node);
    cudaGetSymbolAddress((void**)&tmp,  g_tmp);
    cudaGetSymbolAddress((void**)&agg,  g_agg);
    cudaGetSymbolAddress((void**)&gi,   g_gi);
    cudaGetSymbolAddress((void**)&gh,   g_gh);
    cudaGetSymbolAddress((void**)&wiht, g_wiht);
    cudaGetSymbolAddress((void**)&whht, g_whht);

    const int GEMM_SMEM = (128*256 + 128*128)*sizeof(float); // 196608
    const int AGG_SMEM  = (256*128 + 16*256)*sizeof(float);  // 147456
    cudaFuncSetAttribute(k_gemm, cudaFuncAttributeMaxDynamicSharedMemorySize, GEMM_SMEM);
    cudaFuncSetAttribute(k_agg,  cudaFuncAttributeMaxDynamicSharedMemorySize, AGG_SMEM);

    k_transpose<<<(H3*Hq + 255)/256, 256>>>(w_ih, wiht);
    k_transpose<<<(H3*Hq + 255)/256, 256>>>(w_hh, whht);
    k_gather<<<NROW*32/256, 256>>>(input_var, embed, node);

    for (int it = 0; it < NLOOP; it++){
        // tmp = node @ gnn_w + gnn_b
        k_gemm<<<dim3(NROW/256,1), 512, GEMM_SMEM>>>(node, gnn_w, 128, gnn_b, tmp, 128, 0);
        // agg[b,d] = adjacency[b,d] @ tmp[b,d]
        k_agg<<<BDq, 512, AGG_SMEM>>>(adjacency, tmp, agg);
        // gi = agg @ w_ih^T + b_ih ; gh = node @ w_hh^T + b_hh  (3 col chunks via gridDim.y)
        k_gemm<<<dim3(NROW/256,3), 512, GEMM_SMEM>>>(agg,  wiht, H3, b_ih, gi, H3, 0);
        k_gemm<<<dim3(NROW/256,3), 512, GEMM_SMEM>>>(node, whht, H3, b_hh, gh, H3, 0);
        k_gru<<<NROW*32/256, 256>>>(gi, gh, node);
    }

    // MLP head
    k_gemm<<<dim3(NROW/256,1), 512, GEMM_SMEM>>>(node, mlp_w1, 128, mlp_b1, tmp, 128, 1);
    k_gemm<<<dim3(NROW/256,1), 512, GEMM_SMEM>>>(tmp,  mlp_w2, 128, mlp_b2, agg, 128, 1);
    k_final<<<NROW/8, 256>>>(agg, mlp_w3, mlp_b3, out);
}

// round 15
// speedup vs baseline: 1.5153x; 1.0391x over previous
#include <cuda_runtime.h>
#include <math.h>

// Problem constants
#define Bq 16
#define Dq 64
#define Sq 256
#define Hq 128
#define H3 384
#define NROW (Bq*Dq*Sq)   // 262144
#define BDq (Bq*Dq)       // 1024
#define NLOOP 10

// Scratch (device globals: allocation-free rule)
__device__ float g_node[NROW*Hq];
__device__ float g_tmp [NROW*Hq];
__device__ float g_agg [NROW*Hq];
__device__ float g_gi  [NROW*H3];
__device__ float g_gh  [NROW*H3];
__device__ float g_wiht[Hq*H3];
__device__ float g_whht[Hq*H3];

// ---------------------------------------------------------------------------
// Packed fp32x2 FMA (sm_103a FFMA2): two independent IEEE-rn fp32 FMAs.
// ---------------------------------------------------------------------------
__device__ __forceinline__ unsigned long long splat2(float x){
    unsigned long long r;
    unsigned u = __float_as_uint(x);
    asm("mov.b64 %0, {%1, %1};" : "=l"(r) : "r"(u));
    return r;
}
__device__ __forceinline__ unsigned long long fma2(unsigned long long a,
                                                   unsigned long long b,
                                                   unsigned long long c){
    unsigned long long d;
    asm("fma.rn.f32x2 %0, %1, %2, %3;" : "=l"(d) : "l"(a), "l"(b), "l"(c));
    return d;
}
__device__ __forceinline__ float2 unpack2(unsigned long long p){
    unsigned lo, hi;
    asm("mov.b64 {%0, %1}, %2;" : "=r"(lo), "=r"(hi) : "l"(p));
    return make_float2(__uint_as_float(lo), __uint_as_float(hi));
}

// ---------------------------------------------------------------------------
// FROZEN NUMERICS (R10-verified): XLA EmitFastTanh, unfused mul/add.
// ---------------------------------------------------------------------------
__device__ __forceinline__ float tanh_xla(float x){
    float ax = fabsf(x);
    if (ax < 0.0004f) return x;
    float xc = fminf(fmaxf(x, -7.90531110763549805f), 7.90531110763549805f);
    float a  = __fmul_rn(xc, xc);
    float p = __fadd_rn(__fmul_rn(a, -2.76076847742355e-16f), 2.00018790482477e-13f);
    p = __fadd_rn(__fmul_rn(a, p), -8.60467152213735e-11f);
    p = __fadd_rn(__fmul_rn(a, p),  5.12229709037114e-08f);
    p = __fadd_rn(__fmul_rn(a, p),  1.48572235717979e-05f);
    p = __fadd_rn(__fmul_rn(a, p),  6.37261928875436e-04f);
    p = __fadd_rn(__fmul_rn(a, p),  4.89352455891786e-03f);
    float num = __fmul_rn(xc, p);
    float q = __fadd_rn(__fmul_rn(a, 1.19825839466702e-06f), 1.18534705686654e-04f);
    q = __fadd_rn(__fmul_rn(a, q), 2.26843463243900e-03f);
    q = __fadd_rn(__fmul_rn(a, q), 4.89352518554385e-03f);
    return __fdiv_rn(num, q);
}

// FROZEN: Cephes/Eigen f32 exp, unfused.
__device__ __forceinline__ float exp_cephes(float x){
    x = fminf(x,  88.3762626647950f);
    x = fmaxf(x, -88.3762626647949f);
    float m = floorf(__fadd_rn(__fmul_rn(x, 1.44269504088896341f), 0.5f));
    float r = __fsub_rn(x, __fmul_rn(m, 0.693359375f));
    r = __fsub_rn(r, __fmul_rn(m, -2.12194440e-4f));
    float z = __fmul_rn(r, r);
    float y = 1.9875691500e-4f;
    y = __fadd_rn(__fmul_rn(y, r), 1.3981999507e-3f);
    y = __fadd_rn(__fmul_rn(y, r), 8.3334519073e-3f);
    y = __fadd_rn(__fmul_rn(y, r), 4.1665795894e-2f);
    y = __fadd_rn(__fmul_rn(y, r), 1.6666665459e-1f);
    y = __fadd_rn(__fmul_rn(y, r), 5.0000001201e-1f);
    y = __fadd_rn(__fmul_rn(y, z), r);
    y = __fadd_rn(y, 1.0f);
    int mi = (int)m;
    float s = __int_as_float((mi + 127) << 23);
    return __fmul_rn(y, s);
}

__device__ __forceinline__ float sigmoid_xla(float x){
    float e = exp_cephes(-x);
    return __fdiv_rn(1.f, __fadd_rn(1.f, e));
}

// ---------------------------------------------------------------------------
// Embedding gather
// ---------------------------------------------------------------------------
__global__ void k_gather(const int* __restrict__ idx,
                         const float* __restrict__ embed,
                         float* __restrict__ node)
{
    size_t t = (size_t)blockIdx.x*blockDim.x + threadIdx.x;
    size_t n = t >> 5; int c = (int)(t & 31) << 2;
    float4 v = *(const float4*)(embed + (size_t)idx[n]*Hq + c);
    *(float4*)(node + n*Hq + c) = v;
}

// ---------------------------------------------------------------------------
// Weight transpose: wt[k][j] = w[j][k], w is [H3][Hq]
// ---------------------------------------------------------------------------
__global__ void k_transpose(const float* __restrict__ w, float* __restrict__ wt)
{
    int t = blockIdx.x*blockDim.x + threadIdx.x;
    if (t < H3*Hq){ int j = t / Hq, k = t % Hq; wt[k*H3 + j] = w[t]; }
}

// ---------------------------------------------------------------------------
// GEMM: software-pipelined f32x2 inner loop (same per-output chains).
// 512 threads, 256 rows x 128 cols, tile 8x8.
// ---------------------------------------------------------------------------
__global__ __launch_bounds__(512, 1)
void k_gemm(const float* __restrict__ A,
            const float* __restrict__ W, int ldw,
            const float* __restrict__ bias,
            float* __restrict__ C, int ldc, int act)
{
    extern __shared__ float smem[];
    float* As = smem;              // 128 k x 256 r
    float* Ws = smem + 128*256;    // 128 k x 128 c

    const int tid = threadIdx.x;
    const size_t row0 = (size_t)blockIdx.x * 256;
    const int coff = blockIdx.y * 128;
    W += coff;
    C += coff;
    if (bias) bias += coff;

    #pragma unroll
    for (int i = 0; i < 8; i++){
        int f  = tid + i*512;
        int k  = f >> 5;
        int c4 = (f & 31) << 2;
        *(float4*)&Ws[k*128 + c4] = *(const float4*)(W + (size_t)k*ldw + c4);
    }
    #pragma unroll
    for (int i = 0; i < 16; i++){
        int f  = tid + i*512;
        int r  = f & 255;
        int k4 = (f >> 8) << 2;
        float4 v = *(const float4*)(A + (row0 + r)*Hq + k4);
        As[(k4+0)*256 + r] = v.x;
        As[(k4+1)*256 + r] = v.y;
        As[(k4+2)*256 + r] = v.z;
        As[(k4+3)*256 + r] = v.w;
    }
    __syncthreads();

    const int tx = tid & 15, ty = tid >> 4;
    const int cb = tx*8, rb = ty*8;

    unsigned long long acc[8][4];
    #pragma unroll
    for (int i=0;i<8;i++)
        #pragma unroll
        for (int j=0;j<4;j++) acc[i][j] = 0ULL;

    // software pipeline: cur holds operands for k, nxt loads k+1
    float a0[8]; unsigned long long b0[4];
    {
        *(float4*)&a0[0] = *(float4*)&As[rb];
        *(float4*)&a0[4] = *(float4*)&As[rb + 4];
        ulonglong2 p01 = *(ulonglong2*)&Ws[cb];
        ulonglong2 p23 = *(ulonglong2*)&Ws[cb + 4];
        b0[0]=p01.x; b0[1]=p01.y; b0[2]=p23.x; b0[3]=p23.y;
    }

    #pragma unroll 4
    for (int k = 0; k < 127; k++){
        float a1[8]; unsigned long long b1[4];
        // prefetch k+1
        *(float4*)&a1[0] = *(float4*)&As[(k+1)*256 + rb];
        *(float4*)&a1[4] = *(float4*)&As[(k+1)*256 + rb + 4];
        ulonglong2 p01 = *(ulonglong2*)&Ws[(k+1)*128 + cb];
        ulonglong2 p23 = *(ulonglong2*)&Ws[(k+1)*128 + cb + 4];
        b1[0]=p01.x; b1[1]=p01.y; b1[2]=p23.x; b1[3]=p23.y;
        // compute k
        #pragma unroll
        for (int i=0;i<8;i++){
            unsigned long long ap = splat2(a0[i]);
            acc[i][0] = fma2(ap, b0[0], acc[i][0]);
            acc[i][1] = fma2(ap, b0[1], acc[i][1]);
            acc[i][2] = fma2(ap, b0[2], acc[i][2]);
            acc[i][3] = fma2(ap, b0[3], acc[i][3]);
        }
        #pragma unroll
        for (int i=0;i<8;i++) a0[i] = a1[i];
        #pragma unroll
        for (int j=0;j<4;j++) b0[j] = b1[j];
    }
    // k = 127
    #pragma unroll
    for (int i=0;i<8;i++){
        unsigned long long ap = splat2(a0[i]);
        acc[i][0] = fma2(ap, b0[0], acc[i][0]);
        acc[i][1] = fma2(ap, b0[1], acc[i][1]);
        acc[i][2] = fma2(ap, b0[2], acc[i][2]);
        acc[i][3] = fma2(ap, b0[3], acc[i][3]);
    }

    float bv[8];
    #pragma unroll
    for (int j=0;j<8;j++) bv[j] = bias ? bias[cb+j] : 0.f;

    #pragma unroll
    for (int i=0;i<8;i++){
        float* crow = C + (row0 + rb + i)*(size_t)ldc + cb;
        float o[8];
        #pragma unroll
        for (int j=0;j<4;j++){
            float2 v2 = unpack2(acc[i][j]);
            float v0 = __fadd_rn(v2.x, bv[j*2+0]);
            float v1 = __fadd_rn(v2.y, bv[j*2+1]);
            o[j*2+0] = act ? tanh_xla(v0) : v0;
            o[j*2+1] = act ? tanh_xla(v1) : v1;
        }
        *(float4*)(crow)   = make_float4(o[0],o[1],o[2],o[3]);
        *(float4*)(crow+4) = make_float4(o[4],o[5],o[6],o[7]);
    }
}

// ---------------------------------------------------------------------------
// Batched aggregation: per (b,d): C[256][128] = A[256][256] @ B[256][128]
// 512 threads, tile 8x8, f32x2; double-buffered Ast staging (DRAM latency
// hidden under the 16-k compute chunk) + register pipeline in chunk.
// ---------------------------------------------------------------------------
__global__ __launch_bounds__(512, 1)
void k_agg(const float* __restrict__ adj,
           const float* __restrict__ tmp,
           float* __restrict__ agg)
{
    extern __shared__ float smem[];
    float* Bs  = smem;               // 256*128   [t][h]
    float* Ast = smem + 256*128;     // 2 x 16*256  [buf][kk][s]

    const int bd = blockIdx.x;
    const float* A  = adj + (size_t)bd*Sq*Sq;
    const float* Bm = tmp + (size_t)bd*Sq*Hq;
    float*       Cm = agg + (size_t)bd*Sq*Hq;
    const int tid = threadIdx.x;

    #pragma unroll
    for (int i = 0; i < 16; i++){
        int f = tid + i*512;
        ((float4*)Bs)[f] = ((const float4*)Bm)[f];
    }

    const int sr  = tid & 255;          // staging row
    const int skh = (tid >> 8) << 3;    // staging k-half (0 or 8)

    // stage chunk 0 into buffer 0
    {
        const float* src = A + (size_t)sr*Sq + skh;
        float4 v0 = *(const float4*)(src);
        float4 v1 = *(const float4*)(src + 4);
        float* dst = Ast;   // buf 0
        dst[(skh+0)*256 + sr] = v0.x; dst[(skh+1)*256 + sr] = v0.y;
        dst[(skh+2)*256 + sr] = v0.z; dst[(skh+3)*256 + sr] = v0.w;
        dst[(skh+4)*256 + sr] = v1.x; dst[(skh+5)*256 + sr] = v1.y;
        dst[(skh+6)*256 + sr] = v1.z; dst[(skh+7)*256 + sr] = v1.w;
    }
    __syncthreads();

    const int hx = tid & 15, sy = tid >> 4;
    const int cb = hx*8, sb = sy*8;

    unsigned long long acc[8][4];
    #pragma unroll
    for (int i=0;i<8;i++)
        #pragma unroll
        for (int j=0;j<4;j++) acc[i][j] = 0ULL;

    for (int k0 = 0; k0 < 256; k0 += 16){
        const int buf = (k0 >> 4) & 1;
        float* cur = Ast + buf*(16*256);
        float* nxt = Ast + (buf^1)*(16*256);
        const bool has_next = (k0 + 16 < 256);

        // issue next chunk's global loads early (latency hidden by compute)
        float4 v0, v1;
        if (has_next){
            const float* src = A + (size_t)sr*Sq + (k0+16) + skh;
            v0 = *(const float4*)(src);
            v1 = *(const float4*)(src + 4);
        }

        // compute 16 k's from cur, register-pipelined
        {
            float a0[8]; unsigned long long b0[4];
            *(float4*)&a0[0] = *(float4*)&cur[sb];
            *(float4*)&a0[4] = *(float4*)&cur[sb + 4];
            ulonglong2 p01 = *(ulonglong2*)&Bs[(k0)*128 + cb];
            ulonglong2 p23 = *(ulonglong2*)&Bs[(k0)*128 + cb + 4];
            b0[0]=p01.x; b0[1]=p01.y; b0[2]=p23.x; b0[3]=p23.y;

            #pragma unroll
            for (int kk = 0; kk < 15; kk++){
                float a1[8]; unsigned long long b1[4];
                *(float4*)&a1[0] = *(float4*)&cur[(kk+1)*256 + sb];
                *(float4*)&a1[4] = *(float4*)&cur[(kk+1)*256 + sb + 4];
                ulonglong2 q01 = *(ulonglong2*)&Bs[(k0+kk+1)*128 + cb];
                ulonglong2 q23 = *(ulonglong2*)&Bs[(k0+kk+1)*128 + cb + 4];
                b1[0]=q01.x; b1[1]=q01.y; b1[2]=q23.x; b1[3]=q23.y;
                #pragma unroll
                for (int i=0;i<8;i++){
                    unsigned long long ap = splat2(a0[i]);
                    acc[i][0] = fma2(ap, b0[0], acc[i][0]);
                    acc[i][1] = fma2(ap, b0[1], acc[i][1]);
                    acc[i][2] = fma2(ap, b0[2], acc[i][2]);
                    acc[i][3] = fma2(ap, b0[3], acc[i][3]);
                }
                #pragma unroll
                for (int i=0;i<8;i++) a0[i] = a1[i];
                #pragma unroll
                for (int j=0;j<4;j++) b0[j] = b1[j];
            }
            #pragma unroll
            for (int i=0;i<8;i++){
                unsigned long long ap = splat2(a0[i]);
                acc[i][0] = fma2(ap, b0[0], acc[i][0]);
                acc[i][1] = fma2(ap, b0[1], acc[i][1]);
                acc[i][2] = fma2(ap, b0[2], acc[i][2]);
                acc[i][3] = fma2(ap, b0[3], acc[i][3]);
            }
        }

        // store staged data into the other buffer
        if (has_next){
            nxt[(skh+0)*256 + sr] = v0.x; nxt[(skh+1)*256 + sr] = v0.y;
            nxt[(skh+2)*256 + sr] = v0.z; nxt[(skh+3)*256 + sr] = v0.w;
            nxt[(skh+4)*256 + sr] = v1.x; nxt[(skh+5)*256 + sr] = v1.y;
            nxt[(skh+6)*256 + sr] = v1.z; nxt[(skh+7)*256 + sr] = v1.w;
            __syncthreads();
        }
    }

    #pragma unroll
    for (int i=0;i<8;i++){
        float* crow = Cm + (size_t)(sb + i)*Hq + cb;
        float2 v0 = unpack2(acc[i][0]);
        float2 v1 = unpack2(acc[i][1]);
        float2 v2 = unpack2(acc[i][2]);
        float2 v3 = unpack2(acc[i][3]);
        *(float4*)(crow)   = make_float4(v0.x, v0.y, v1.x, v1.y);
        *(float4*)(crow+4) = make_float4(v2.x, v2.y, v3.x, v3.y);
    }
}

// ---------------------------------------------------------------------------
// GRU elementwise combine — FROZEN numerics.
// ---------------------------------------------------------------------------
__device__ __forceinline__ float gru1(float ir,float iz,float inn,
                                      float hr,float hz,float hn,float h){
    float r  = sigmoid_xla(__fadd_rn(ir, hr));
    float z  = sigmoid_xla(__fadd_rn(iz, hz));
    float rhn = __fmul_rn(r, hn);
    float ng  = tanh_xla(__fadd_rn(inn, rhn));
    float omz = __fsub_rn(1.f, z);
    float t0  = __fmul_rn(omz, ng);
    float t1  = __fmul_rn(z, h);
    return __fadd_rn(t0, t1);
}

__global__ void k_gru(const float* __restrict__ gi,
                      const float* __restrict__ gh,
                      float* __restrict__ node)
{
    size_t t = (size_t)blockIdx.x*blockDim.x + threadIdx.x;
    size_t n = t >> 5; int c = (int)(t & 31) << 2;
    const float* gin = gi + n*H3 + c;
    const float* ghn = gh + n*H3 + c;
    float* hp = node + n*Hq + c;
    float4 ir  = *(const float4*)(gin);
    float4 iz  = *(const float4*)(gin + 128);
    float4 inn = *(const float4*)(gin + 256);
    float4 hr  = *(const float4*)(ghn);
    float4 hz  = *(const float4*)(ghn + 128);
    float4 hn  = *(const float4*)(ghn + 256);
    float4 h   = *(float4*)hp;
    float4 o;
    o.x = gru1(ir.x,iz.x,inn.x,hr.x,hz.x,hn.x,h.x);
    o.y = gru1(ir.y,iz.y,inn.y,hr.y,hz.y,hn.y,h.y);
    o.z = gru1(ir.z,iz.z,inn.z,hr.z,hz.z,hn.z,h.z);
    o.w = gru1(ir.w,iz.w,inn.w,hr.w,hz.w,hn.w,h.w);
    *(float4*)hp = o;
}

// ---------------------------------------------------------------------------
// Final: out[n] = tanh(dot(t2[n], w3) + b3), one warp per row
// ---------------------------------------------------------------------------
__global__ void k_final(const float* __restrict__ t2,
                        const float* __restrict__ w3,
                        const float* __restrict__ b3,
                        float* __restrict__ out)
{
    size_t row = ((size_t)blockIdx.x*blockDim.x + threadIdx.x) >> 5;
    int lane = threadIdx.x & 31;
    const float* a = t2 + row*Hq + lane*4;
    const float* w = w3 + lane*4;
    float p = 0.f;
    #pragma unroll
    for (int q=0;q<4;q++) p = fmaf(a[q], w[q], p);
    #pragma unroll
    for (int o = 16; o; o >>= 1) p = __fadd_rn(p, __shfl_xor_sync(0xFFFFFFFFu, p, o));
    if (lane == 0) out[row] = tanh_xla(__fadd_rn(p, b3[0]));
}

// ---------------------------------------------------------------------------
extern "C" void kernel_launch(void* const* d_in, const int* in_sizes, int n_in,
                              void* d_out, int out_size)
{
    const int*   input_var = (const int*)  d_in[0];
    const float* adjacency = (const float*)d_in[1];
    const float* embed     = (const float*)d_in[2];
    const float* gnn_w     = (const float*)d_in[3];
    const float* gnn_b     = (const float*)d_in[4];
    const float* w_ih      = (const float*)d_in[5];
    const float* w_hh      = (const float*)d_in[6];
    const float* b_ih      = (const float*)d_in[7];
    const float* b_hh      = (const float*)d_in[8];
    const float* mlp_w1    = (const float*)d_in[9];
    const float* mlp_b1    = (const float*)d_in[10];
    const float* mlp_w2    = (const float*)d_in[11];
    const float* mlp_b2    = (const float*)d_in[12];
    const float* mlp_w3    = (const float*)d_in[13];
    const float* mlp_b3    = (const float*)d_in[14];
    float* out = (float*)d_out;

    float *node,*tmp,*agg,*gi,*gh,*wiht,*whht;
    cudaGetSymbolAddress((void**)&node, g_node);
    cudaGetSymbolAddress((void**)&tmp,  g_tmp);
    cudaGetSymbolAddress((void**)&agg,  g_agg);
    cudaGetSymbolAddress((void**)&gi,   g_gi);
    cudaGetSymbolAddress((void**)&gh,   g_gh);
    cudaGetSymbolAddress((void**)&wiht, g_wiht);
    cudaGetSymbolAddress((void**)&whht, g_whht);

    const int GEMM_SMEM = (128*256 + 128*128)*sizeof(float);   // 196608
    const int AGG_SMEM  = (256*128 + 2*16*256)*sizeof(float);  // 163840
    cudaFuncSetAttribute(k_gemm, cudaFuncAttributeMaxDynamicSharedMemorySize, GEMM_SMEM);
    cudaFuncSetAttribute(k_agg,  cudaFuncAttributeMaxDynamicSharedMemorySize, AGG_SMEM);

    k_transpose<<<(H3*Hq + 255)/256, 256>>>(w_ih, wiht);
    k_transpose<<<(H3*Hq + 255)/256, 256>>>(w_hh, whht);
    k_gather<<<NROW*32/256, 256>>>(input_var, embed, node);

    for (int it = 0; it < NLOOP; it++){
        k_gemm<<<dim3(NROW/256,1), 512, GEMM_SMEM>>>(node, gnn_w, 128, gnn_b, tmp, 128, 0);
        k_agg<<<BDq, 512, AGG_SMEM>>>(adjacency, tmp, agg);
        k_gemm<<<dim3(NROW/256,3), 512, GEMM_SMEM>>>(agg,  wiht, H3, b_ih, gi, H3, 0);
        k_gemm<<<dim3(NROW/256,3), 512, GEMM_SMEM>>>(node, whht, H3, b_hh, gh, H3, 0);
        k_gru<<<NROW*32/256, 256>>>(gi, gh, node);
    }

    // MLP head
    k_gemm<<<dim3(NROW/256,1), 512, GEMM_SMEM>>>(node, mlp_w1, 128, mlp_b1, tmp, 128, 1);
    k_gemm<<<dim3(NROW/256,1), 512, GEMM_SMEM>>>(tmp,  mlp_w2, 128, mlp_b2, agg, 128, 1);
    k_final<<<NROW/8, 256>>>(agg, mlp_w3, mlp_b3, out);
}

// round 16
// speedup vs baseline: 1.6112x; 1.0633x over previous
#include <cuda_runtime.h>
#include <math.h>

// Problem constants
#define Bq 16
#define Dq 64
#define Sq 256
#define Hq 128
#define H3 384
#define NROW (Bq*Dq*Sq)   // 262144
#define BDq (Bq*Dq)       // 1024
#define NLOOP 10

// Scratch (device globals: allocation-free rule)
__device__ float g_node[NROW*Hq];
__device__ float g_tmp [NROW*Hq];
__device__ float g_agg [NROW*Hq];
__device__ float g_gi  [NROW*H3];
__device__ float g_gh  [NROW*H3];
__device__ float g_wiht[Hq*H3];
__device__ float g_whht[Hq*H3];

// ---------------------------------------------------------------------------
// Packed fp32x2 FMA (sm_103a FFMA2): two independent IEEE-rn fp32 FMAs.
// ---------------------------------------------------------------------------
__device__ __forceinline__ unsigned long long splat2(float x){
    unsigned long long r;
    unsigned u = __float_as_uint(x);
    asm("mov.b64 %0, {%1, %1};" : "=l"(r) : "r"(u));
    return r;
}
__device__ __forceinline__ unsigned long long fma2(unsigned long long a,
                                                   unsigned long long b,
                                                   unsigned long long c){
    unsigned long long d;
    asm("fma.rn.f32x2 %0, %1, %2, %3;" : "=l"(d) : "l"(a), "l"(b), "l"(c));
    return d;
}
__device__ __forceinline__ float2 unpack2(unsigned long long p){
    unsigned lo, hi;
    asm("mov.b64 {%0, %1}, %2;" : "=r"(lo), "=r"(hi) : "l"(p));
    return make_float2(__uint_as_float(lo), __uint_as_float(hi));
}

// ---------------------------------------------------------------------------
// FROZEN NUMERICS (R10-verified): XLA EmitFastTanh, unfused mul/add.
// ---------------------------------------------------------------------------
__device__ __forceinline__ float tanh_xla(float x){
    float ax = fabsf(x);
    if (ax < 0.0004f) return x;
    float xc = fminf(fmaxf(x, -7.90531110763549805f), 7.90531110763549805f);
    float a  = __fmul_rn(xc, xc);
    float p = __fadd_rn(__fmul_rn(a, -2.76076847742355e-16f), 2.00018790482477e-13f);
    p = __fadd_rn(__fmul_rn(a, p), -8.60467152213735e-11f);
    p = __fadd_rn(__fmul_rn(a, p),  5.12229709037114e-08f);
    p = __fadd_rn(__fmul_rn(a, p),  1.48572235717979e-05f);
    p = __fadd_rn(__fmul_rn(a, p),  6.37261928875436e-04f);
    p = __fadd_rn(__fmul_rn(a, p),  4.89352455891786e-03f);
    float num = __fmul_rn(xc, p);
    float q = __fadd_rn(__fmul_rn(a, 1.19825839466702e-06f), 1.18534705686654e-04f);
    q = __fadd_rn(__fmul_rn(a, q), 2.26843463243900e-03f);
    q = __fadd_rn(__fmul_rn(a, q), 4.89352518554385e-03f);
    return __fdiv_rn(num, q);
}

// FROZEN: Cephes/Eigen f32 exp, unfused.
__device__ __forceinline__ float exp_cephes(float x){
    x = fminf(x,  88.3762626647950f);
    x = fmaxf(x, -88.3762626647949f);
    float m = floorf(__fadd_rn(__fmul_rn(x, 1.44269504088896341f), 0.5f));
    float r = __fsub_rn(x, __fmul_rn(m, 0.693359375f));
    r = __fsub_rn(r, __fmul_rn(m, -2.12194440e-4f));
    float z = __fmul_rn(r, r);
    float y = 1.9875691500e-4f;
    y = __fadd_rn(__fmul_rn(y, r), 1.3981999507e-3f);
    y = __fadd_rn(__fmul_rn(y, r), 8.3334519073e-3f);
    y = __fadd_rn(__fmul_rn(y, r), 4.1665795894e-2f);
    y = __fadd_rn(__fmul_rn(y, r), 1.6666665459e-1f);
    y = __fadd_rn(__fmul_rn(y, r), 5.0000001201e-1f);
    y = __fadd_rn(__fmul_rn(y, z), r);
    y = __fadd_rn(y, 1.0f);
    int mi = (int)m;
    float s = __int_as_float((mi + 127) << 23);
    return __fmul_rn(y, s);
}

__device__ __forceinline__ float sigmoid_xla(float x){
    float e = exp_cephes(-x);
    return __fdiv_rn(1.f, __fadd_rn(1.f, e));
}

// ---------------------------------------------------------------------------
// Embedding gather
// ---------------------------------------------------------------------------
__global__ void k_gather(const int* __restrict__ idx,
                         const float* __restrict__ embed,
                         float* __restrict__ node)
{
    size_t t = (size_t)blockIdx.x*blockDim.x + threadIdx.x;
    size_t n = t >> 5; int c = (int)(t & 31) << 2;
    float4 v = *(const float4*)(embed + (size_t)idx[n]*Hq + c);
    *(float4*)(node + n*Hq + c) = v;
}

// ---------------------------------------------------------------------------
// Weight transpose: wt[k][j] = w[j][k], w is [H3][Hq]
// ---------------------------------------------------------------------------
__global__ void k_transpose(const float* __restrict__ w, float* __restrict__ wt)
{
    int t = blockIdx.x*blockDim.x + threadIdx.x;
    if (t < H3*Hq){ int j = t / Hq, k = t % Hq; wt[k*H3 + j] = w[t]; }
}

// Load helpers for the 16x8 row-paired tile (used via macros for reg control)
#define GEMM_LOAD(kidx, ap, b) do { \
    ulonglong2 t0 = *(ulonglong2*)&As[(kidx)*256 + rb]; \
    ulonglong2 t1 = *(ulonglong2*)&As[(kidx)*256 + rb + 4]; \
    ulonglong2 t2 = *(ulonglong2*)&As[(kidx)*256 + rb + 8]; \
    ulonglong2 t3 = *(ulonglong2*)&As[(kidx)*256 + rb + 12]; \
    ap[0]=t0.x; ap[1]=t0.y; ap[2]=t1.x; ap[3]=t1.y; \
    ap[4]=t2.x; ap[5]=t2.y; ap[6]=t3.x; ap[7]=t3.y; \
    *(float4*)&b[0] = *(float4*)&Ws[(kidx)*128 + cb]; \
    *(float4*)&b[4] = *(float4*)&Ws[(kidx)*128 + cb + 4]; \
} while(0)

#define GEMM_COMP(ap, b) do { \
    _Pragma("unroll") \
    for (int j=0;j<8;j++){ \
        unsigned long long bs = splat2(b[j]); \
        _Pragma("unroll") \
        for (int p=0;p<8;p++) acc[p][j] = fma2(ap[p], bs, acc[p][j]); \
    } \
} while(0)

// ---------------------------------------------------------------------------
// GEMM: C[row][c] = sum_k A[row][k]*W[k*ldw+c] (+bias, opt tanh)
// 256 threads, 256 rows x 128 cols block, thread tile 16 rows x 8 cols.
// Row-paired f32x2 accumulators: a-pairs loaded directly (no splat),
// b splatted. Copy-free ping-pong pipeline. Per-output chains bit-identical.
// ---------------------------------------------------------------------------
__global__ __launch_bounds__(256, 1)
void k_gemm(const float* __restrict__ A,
            const float* __restrict__ W, int ldw,
            const float* __restrict__ bias,
            float* __restrict__ C, int ldc, int act)
{
    extern __shared__ float smem[];
    float* As = smem;              // 128 k x 256 r
    float* Ws = smem + 128*256;    // 128 k x 128 c

    const int tid = threadIdx.x;
    const size_t row0 = (size_t)blockIdx.x * 256;
    const int coff = blockIdx.y * 128;
    W += coff;
    C += coff;
    if (bias) bias += coff;

    #pragma unroll
    for (int i = 0; i < 16; i++){
        int f  = tid + i*256;           // 0..4095
        int k  = f >> 5;
        int c4 = (f & 31) << 2;
        *(float4*)&Ws[k*128 + c4] = *(const float4*)(W + (size_t)k*ldw + c4);
    }
    #pragma unroll
    for (int i = 0; i < 32; i++){
        int f  = tid + i*256;           // 0..8191
        int r  = f & 255;
        int k4 = (f >> 8) << 2;
        float4 v = *(const float4*)(A + (row0 + r)*Hq + k4);
        As[(k4+0)*256 + r] = v.x;
        As[(k4+1)*256 + r] = v.y;
        As[(k4+2)*256 + r] = v.z;
        As[(k4+3)*256 + r] = v.w;
    }
    __syncthreads();

    const int tx = tid & 15, ty = tid >> 4;   // tx: col group 0..15, ty: row group 0..15
    const int cb = tx*8, rb = ty*16;

    unsigned long long acc[8][8];             // row-pair p x col j
    #pragma unroll
    for (int p=0;p<8;p++)
        #pragma unroll
        for (int j=0;j<8;j++) acc[p][j] = 0ULL;

    unsigned long long ap0[8], ap1[8];
    float b0[8], b1[8];
    GEMM_LOAD(0, ap0, b0);
    #pragma unroll 7
    for (int k = 0; k < 126; k += 2){
        GEMM_LOAD(k+1, ap1, b1);
        GEMM_COMP(ap0, b0);
        GEMM_LOAD(k+2, ap0, b0);
        GEMM_COMP(ap1, b1);
    }
    GEMM_LOAD(127, ap1, b1);
    GEMM_COMP(ap0, b0);   // k = 126
    GEMM_COMP(ap1, b1);   // k = 127

    float bv[8];
    #pragma unroll
    for (int j=0;j<8;j++) bv[j] = bias ? bias[cb+j] : 0.f;

    #pragma unroll
    for (int p=0;p<8;p++){
        float olo[8], ohi[8];
        #pragma unroll
        for (int j=0;j<8;j++){
            float2 v = unpack2(acc[p][j]);
            float vlo = __fadd_rn(v.x, bv[j]);
            float vhi = __fadd_rn(v.y, bv[j]);
            olo[j] = act ? tanh_xla(vlo) : vlo;
            ohi[j] = act ? tanh_xla(vhi) : vhi;
        }
        float* r0p = C + (row0 + rb + 2*p    )*(size_t)ldc + cb;
        float* r1p = C + (row0 + rb + 2*p + 1)*(size_t)ldc + cb;
        *(float4*)(r0p)   = make_float4(olo[0],olo[1],olo[2],olo[3]);
        *(float4*)(r0p+4) = make_float4(olo[4],olo[5],olo[6],olo[7]);
        *(float4*)(r1p)   = make_float4(ohi[0],ohi[1],ohi[2],ohi[3]);
        *(float4*)(r1p+4) = make_float4(ohi[4],ohi[5],ohi[6],ohi[7]);
    }
}

#define AGG_LOAD(kk, ap, b) do { \
    ulonglong2 t0 = *(ulonglong2*)&cur[(kk)*256 + rb]; \
    ulonglong2 t1 = *(ulonglong2*)&cur[(kk)*256 + rb + 4]; \
    ulonglong2 t2 = *(ulonglong2*)&cur[(kk)*256 + rb + 8]; \
    ulonglong2 t3 = *(ulonglong2*)&cur[(kk)*256 + rb + 12]; \
    ap[0]=t0.x; ap[1]=t0.y; ap[2]=t1.x; ap[3]=t1.y; \
    ap[4]=t2.x; ap[5]=t2.y; ap[6]=t3.x; ap[7]=t3.y; \
    *(float4*)&b[0] = *(float4*)&Bs[(k0+(kk))*128 + cb]; \
    *(float4*)&b[4] = *(float4*)&Bs[(k0+(kk))*128 + cb + 4]; \
} while(0)

// ---------------------------------------------------------------------------
// Batched aggregation: per (b,d): C[256][128] = A[256][256] @ B[256][128]
// 256 threads, thread tile 16x8 row-paired f32x2; double-buffered Ast
// staging (DRAM latency hidden); copy-free ping-pong within each chunk.
// ---------------------------------------------------------------------------
__global__ __launch_bounds__(256, 1)
void k_agg(const float* __restrict__ adj,
           const float* __restrict__ tmp,
           float* __restrict__ agg)
{
    extern __shared__ float smem[];
    float* Bs  = smem;               // 256*128   [t][h]
    float* Ast = smem + 256*128;     // 2 x 16*256  [buf][kk][s]

    const int bd = blockIdx.x;
    const float* A  = adj + (size_t)bd*Sq*Sq;
    const float* Bm = tmp + (size_t)bd*Sq*Hq;
    float*       Cm = agg + (size_t)bd*Sq*Hq;
    const int tid = threadIdx.x;

    #pragma unroll
    for (int i = 0; i < 32; i++){
        int f = tid + i*256;
        ((float4*)Bs)[f] = ((const float4*)Bm)[f];
    }

    // staging: thread tid stages row sr = tid, 16 k's per chunk
    const int sr = tid;

    // stage chunk 0 into buffer 0
    {
        const float* src = A + (size_t)sr*Sq;
        float4 v0 = *(const float4*)(src);
        float4 v1 = *(const float4*)(src + 4);
        float4 v2 = *(const float4*)(src + 8);
        float4 v3 = *(const float4*)(src + 12);
        float* dst = Ast;
        dst[ 0*256 + sr] = v0.x; dst[ 1*256 + sr] = v0.y;
        dst[ 2*256 + sr] = v0.z; dst[ 3*256 + sr] = v0.w;
        dst[ 4*256 + sr] = v1.x; dst[ 5*256 + sr] = v1.y;
        dst[ 6*256 + sr] = v1.z; dst[ 7*256 + sr] = v1.w;
        dst[ 8*256 + sr] = v2.x; dst[ 9*256 + sr] = v2.y;
        dst[10*256 + sr] = v2.z; dst[11*256 + sr] = v2.w;
        dst[12*256 + sr] = v3.x; dst[13*256 + sr] = v3.y;
        dst[14*256 + sr] = v3.z; dst[15*256 + sr] = v3.w;
    }
    __syncthreads();

    const int tx = tid & 15, ty = tid >> 4;
    const int cb = tx*8, rb = ty*16;

    unsigned long long acc[8][8];
    #pragma unroll
    for (int p=0;p<8;p++)
        #pragma unroll
        for (int j=0;j<8;j++) acc[p][j] = 0ULL;

    for (int k0 = 0; k0 < 256; k0 += 16){
        const int buf = (k0 >> 4) & 1;
        float* cur = Ast + buf*(16*256);
        float* nxt = Ast + (buf^1)*(16*256);
        const bool has_next = (k0 + 16 < 256);

        // issue next chunk's global loads early
        float4 v0, v1, v2, v3;
        if (has_next){
            const float* src = A + (size_t)sr*Sq + (k0+16);
            v0 = *(const float4*)(src);
            v1 = *(const float4*)(src + 4);
            v2 = *(const float4*)(src + 8);
            v3 = *(const float4*)(src + 12);
        }

        // compute 16 k's from cur, copy-free ping-pong
        {
            unsigned long long ap0[8], ap1[8];
            float b0[8], b1[8];
            AGG_LOAD(0, ap0, b0);
            #pragma unroll
            for (int kk = 0; kk < 14; kk += 2){
                AGG_LOAD(kk+1, ap1, b1);
                GEMM_COMP(ap0, b0);
                AGG_LOAD(kk+2, ap0, b0);
                GEMM_COMP(ap1, b1);
            }
            AGG_LOAD(15, ap1, b1);
            GEMM_COMP(ap0, b0);   // kk = 14
            GEMM_COMP(ap1, b1);   // kk = 15
        }

        if (has_next){
            nxt[ 0*256 + sr] = v0.x; nxt[ 1*256 + sr] = v0.y;
            nxt[ 2*256 + sr] = v0.z; nxt[ 3*256 + sr] = v0.w;
            nxt[ 4*256 + sr] = v1.x; nxt[ 5*256 + sr] = v1.y;
            nxt[ 6*256 + sr] = v1.z; nxt[ 7*256 + sr] = v1.w;
            nxt[ 8*256 + sr] = v2.x; nxt[ 9*256 + sr] = v2.y;
            nxt[10*256 + sr] = v2.z; nxt[11*256 + sr] = v2.w;
            nxt[12*256 + sr] = v3.x; nxt[13*256 + sr] = v3.y;
            nxt[14*256 + sr] = v3.z; nxt[15*256 + sr] = v3.w;
            __syncthreads();
        }
    }

    #pragma unroll
    for (int p=0;p<8;p++){
        float* r0p = Cm + (size_t)(rb + 2*p    )*Hq + cb;
        float* r1p = Cm + (size_t)(rb + 2*p + 1)*Hq + cb;
        float olo[8], ohi[8];
        #pragma unroll
        for (int j=0;j<8;j++){
            float2 v = unpack2(acc[p][j]);
            olo[j] = v.x; ohi[j] = v.y;
        }
        *(float4*)(r0p)   = make_float4(olo[0],olo[1],olo[2],olo[3]);
        *(float4*)(r0p+4) = make_float4(olo[4],olo[5],olo[6],olo[7]);
        *(float4*)(r1p)   = make_float4(ohi[0],ohi[1],ohi[2],ohi[3]);
        *(float4*)(r1p+4) = make_float4(ohi[4],ohi[5],ohi[6],ohi[7]);
    }
}

// ---------------------------------------------------------------------------
// GRU elementwise combine — FROZEN numerics.
// ---------------------------------------------------------------------------
__device__ __forceinline__ float gru1(float ir,float iz,float inn,
                                      float hr,float hz,float hn,float h){
    float r  = sigmoid_xla(__fadd_rn(ir, hr));
    float z  = sigmoid_xla(__fadd_rn(iz, hz));
    float rhn = __fmul_rn(r, hn);
    float ng  = tanh_xla(__fadd_rn(inn, rhn));
    float omz = __fsub_rn(1.f, z);
    float t0  = __fmul_rn(omz, ng);
    float t1  = __fmul_rn(z, h);
    return __fadd_rn(t0, t1);
}

__global__ void k_gru(const float* __restrict__ gi,
                      const float* __restrict__ gh,
                      float* __restrict__ node)
{
    size_t t = (size_t)blockIdx.x*blockDim.x + threadIdx.x;
    size_t n = t >> 5; int c = (int)(t & 31) << 2;
    const float* gin = gi + n*H3 + c;
    const float* ghn = gh + n*H3 + c;
    float* hp = node + n*Hq + c;
    float4 ir  = *(const float4*)(gin);
    float4 iz  = *(const float4*)(gin + 128);
    float4 inn = *(const float4*)(gin + 256);
    float4 hr  = *(const float4*)(ghn);
    float4 hz  = *(const float4*)(ghn + 128);
    float4 hn  = *(const float4*)(ghn + 256);
    float4 h   = *(float4*)hp;
    float4 o;
    o.x = gru1(ir.x,iz.x,inn.x,hr.x,hz.x,hn.x,h.x);
    o.y = gru1(ir.y,iz.y,inn.y,hr.y,hz.y,hn.y,h.y);
    o.z = gru1(ir.z,iz.z,inn.z,hr.z,hz.z,hn.z,h.z);
    o.w = gru1(ir.w,iz.w,inn.w,hr.w,hz.w,hn.w,h.w);
    *(float4*)hp = o;
}

// ---------------------------------------------------------------------------
// Final: out[n] = tanh(dot(t2[n], w3) + b3), one warp per row
// ---------------------------------------------------------------------------
__global__ void k_final(const float* __restrict__ t2,
                        const float* __restrict__ w3,
                        const float* __restrict__ b3,
                        float* __restrict__ out)
{
    size_t row = ((size_t)blockIdx.x*blockDim.x + threadIdx.x) >> 5;
    int lane = threadIdx.x & 31;
    const float* a = t2 + row*Hq + lane*4;
    const float* w = w3 + lane*4;
    float p = 0.f;
    #pragma unroll
    for (int q=0;q<4;q++) p = fmaf(a[q], w[q], p);
    #pragma unroll
    for (int o = 16; o; o >>= 1) p = __fadd_rn(p, __shfl_xor_sync(0xFFFFFFFFu, p, o));
    if (lane == 0) out[row] = tanh_xla(__fadd_rn(p, b3[0]));
}

// ---------------------------------------------------------------------------
extern "C" void kernel_launch(void* const* d_in, const int* in_sizes, int n_in,
                              void* d_out, int out_size)
{
    const int*   input_var = (const int*)  d_in[0];
    const float* adjacency = (const float*)d_in[1];
    const float* embed     = (const float*)d_in[2];
    const float* gnn_w     = (const float*)d_in[3];
    const float* gnn_b     = (const float*)d_in[4];
    const float* w_ih      = (const float*)d_in[5];
    const float* w_hh      = (const float*)d_in[6];
    const float* b_ih      = (const float*)d_in[7];
    const float* b_hh      = (const float*)d_in[8];
    const float* mlp_w1    = (const float*)d_in[9];
    const float* mlp_b1    = (const float*)d_in[10];
    const float* mlp_w2    = (const float*)d_in[11];
    const float* mlp_b2    = (const float*)d_in[12];
    const float* mlp_w3    = (const float*)d_in[13];
    const float* mlp_b3    = (const float*)d_in[14];
    float* out = (float*)d_out;

    float *node,*tmp,*agg,*gi,*gh,*wiht,*whht;
    cudaGetSymbolAddress((void**)&node, g_node);
    cudaGetSymbolAddress((void**)&tmp,  g_tmp);
    cudaGetSymbolAddress((void**)&agg,  g_agg);
    cudaGetSymbolAddress((void**)&gi,   g_gi);
    cudaGetSymbolAddress((void**)&gh,   g_gh);
    cudaGetSymbolAddress((void**)&wiht, g_wiht);
    cudaGetSymbolAddress((void**)&whht, g_whht);

    const int GEMM_SMEM = (128*256 + 128*128)*sizeof(float);   // 196608
    const int AGG_SMEM  = (256*128 + 2*16*256)*sizeof(float);  // 163840
    cudaFuncSetAttribute(k_gemm, cudaFuncAttributeMaxDynamicSharedMemorySize, GEMM_SMEM);
    cudaFuncSetAttribute(k_agg,  cudaFuncAttributeMaxDynamicSharedMemorySize, AGG_SMEM);

    k_transpose<<<(H3*Hq + 255)/256, 256>>>(w_ih, wiht);
    k_transpose<<<(H3*Hq + 255)/256, 256>>>(w_hh, whht);
    k_gather<<<NROW*32/256, 256>>>(input_var, embed, node);

    for (int it = 0; it < NLOOP; it++){
        k_gemm<<<dim3(NROW/256,1), 256, GEMM_SMEM>>>(node, gnn_w, 128, gnn_b, tmp, 128, 0);
        k_agg<<<BDq, 256, AGG_SMEM>>>(adjacency, tmp, agg);
        k_gemm<<<dim3(NROW/256,3), 256, GEMM_SMEM>>>(agg,  wiht, H3, b_ih, gi, H3, 0);
        k_gemm<<<dim3(NROW/256,3), 256, GEMM_SMEM>>>(node, whht, H3, b_hh, gh, H3, 0);
        k_gru<<<NROW*32/256, 256>>>(gi, gh, node);
    }

    // MLP head
    k_gemm<<<dim3(NROW/256,1), 256, GEMM_SMEM>>>(node, mlp_w1, 128, mlp_b1, tmp, 128, 1);
    k_gemm<<<dim3(NROW/256,1), 256, GEMM_SMEM>>>(tmp,  mlp_w2, 128, mlp_b2, agg, 128, 1);
    k_final<<<NROW/8, 256>>>(agg, mlp_w3, mlp_b3, out);
}